// round 12
// baseline (speedup 1.0000x reference)
#include <cuda_runtime.h>
#include <cuda_fp16.h>
#include <cstdint>
#include <cstddef>

// Problem dims (fixed)
#define B_DIM 1024
#define M_DIM 4096
#define W_DIM 2
#define L_DIM 2
#define Z_DIM 64
#define H_DIM 8192   // M*W

// Output layout: x_recon [B*M], logcov [B*M], mu [B*Z], logvar [B*Z]
#define OFF_XREC  0
#define OFF_LCOV  (B_DIM * M_DIM)
#define OFF_MU    (2 * B_DIM * M_DIM)
#define OFF_LV    (2 * B_DIM * M_DIM + B_DIM * Z_DIM)

// -------- scratch (no allocations allowed; __device__ globals) --------
__device__ __half g_xh  [B_DIM * M_DIM];   // x in fp16
__device__ __half g_wch [128 * M_DIM];     // concat(mu_w, lv_w) in fp16
__device__ __half g_h1h [B_DIM * M_DIM];   // encoder layer-1 out (fp16)
__device__ __half g_h2h [B_DIM * M_DIM];   // encoder layer-2 out (fp16)
__device__ float  g_mulv[B_DIM * 128];
__device__ float  g_z[B_DIM * Z_DIM];

__device__ __forceinline__ float sigm(float x) { return 1.0f / (1.0f + expf(-x)); }

#define ACT_NONE 0
#define ACT_RELU 1

// ===================== small fp32 -> fp16 conversion (x, mu_w, lv_w only) ==========
#define NX8 (B_DIM * M_DIM / 8)
#define NC8 (64 * M_DIM / 8)
#define NS8 (NX8 + 2 * NC8)

__device__ __forceinline__ void cvt8(const float* __restrict__ in, __half* __restrict__ out, int j) {
    const float4* p = reinterpret_cast<const float4*>(in) + 2 * (size_t)j;
    float4 a = p[0], b = p[1];
    __half2 h0 = __floats2half2_rn(a.x, a.y);
    __half2 h1 = __floats2half2_rn(a.z, a.w);
    __half2 h2 = __floats2half2_rn(b.x, b.y);
    __half2 h3 = __floats2half2_rn(b.z, b.w);
    uint4 u;
    u.x = *reinterpret_cast<uint32_t*>(&h0);
    u.y = *reinterpret_cast<uint32_t*>(&h1);
    u.z = *reinterpret_cast<uint32_t*>(&h2);
    u.w = *reinterpret_cast<uint32_t*>(&h3);
    reinterpret_cast<uint4*>(out)[j] = u;
}

__global__ void __launch_bounds__(256) f2hS_kernel(
    const float* __restrict__ x, const float* __restrict__ muw,
    const float* __restrict__ lvw,
    __half* __restrict__ xh, __half* __restrict__ wch)
{
    int i = blockIdx.x * 256 + threadIdx.x;
    if (i < NX8)            cvt8(x,   xh,  i);
    else if (i < NX8 + NC8) cvt8(muw, wch, i - NX8);
    else if (i < NS8)       cvt8(lvw, wch + 64 * M_DIM, i - NX8 - NC8);
}

// ===================== common GEMM helpers =====================
__device__ __forceinline__ uint32_t smem_u32(const void* p) {
    uint32_t a;
    asm("{ .reg .u64 t; cvta.to.shared.u64 t, %1; cvt.u32.u64 %0, t; }" : "=r"(a) : "l"(p));
    return a;
}
__device__ __forceinline__ void ldmx4(uint32_t* r, uint32_t addr) {
    asm volatile("ldmatrix.sync.aligned.m8n8.x4.shared.b16 {%0,%1,%2,%3}, [%4];"
                 : "=r"(r[0]), "=r"(r[1]), "=r"(r[2]), "=r"(r[3]) : "r"(addr));
}
__device__ __forceinline__ void mma_f16(float* d, const uint32_t* a, const uint32_t* b) {
    asm volatile(
        "mma.sync.aligned.m16n8k16.row.col.f32.f16.f16.f32 "
        "{%0,%1,%2,%3}, {%4,%5,%6,%7}, {%8,%9}, {%0,%1,%2,%3};\n"
        : "+f"(d[0]), "+f"(d[1]), "+f"(d[2]), "+f"(d[3])
        : "r"(a[0]), "r"(a[1]), "r"(a[2]), "r"(a[3]), "r"(b[0]), "r"(b[1]));
}
__device__ __forceinline__ void cp_async16(uint32_t smem_addr, const void* gptr) {
    asm volatile("cp.async.cg.shared.global [%0], [%1], 16;\n" :: "r"(smem_addr), "l"(gptr));
}
__device__ __forceinline__ void cp_commit() { asm volatile("cp.async.commit_group;\n"); }
template <int N> __device__ __forceinline__ void cp_wait() {
    asm volatile("cp.async.wait_group %0;\n" :: "n"(N));
}
__device__ __forceinline__ uint4 pack8(float4 a, float4 b) {
    __half2 h0 = __floats2half2_rn(a.x, a.y);
    __half2 h1 = __floats2half2_rn(a.z, a.w);
    __half2 h2 = __floats2half2_rn(b.x, b.y);
    __half2 h3 = __floats2half2_rn(b.z, b.w);
    uint4 u;
    u.x = *reinterpret_cast<uint32_t*>(&h0);
    u.y = *reinterpret_cast<uint32_t*>(&h1);
    u.z = *reinterpret_cast<uint32_t*>(&h2);
    u.w = *reinterpret_cast<uint32_t*>(&h3);
    return u;
}

#define HS_ROW   80
#define HS_TILE  (128 * HS_ROW)
#define N_STAGES 4

// ===== encoder GEMM: A fp16 via cp.async (4 stages), W fp32 via LDG+cvt+STS (2 bufs) ====
// C = act(A * W^T + bias), CTA 128x128, 512 threads (16 warps, 32x32 warp tiles), BK=32.
#define WF_SMEM (N_STAGES * HS_TILE + 2 * HS_TILE)   // 61440 B dynamic

template <int ACT>
__global__ void __launch_bounds__(512, 1) gemm_h16_wf32_kernel(
    const __half* __restrict__ A, const float* __restrict__ Wt,
    const float* __restrict__ bias, __half* __restrict__ C,
    int Ndim, int Kdim)
{
    extern __shared__ __align__(16) uint8_t dsm[];
    __shared__ float sbias[128];

    const int tid  = threadIdx.x;
    const int lane = tid & 31;
    const int warp = tid >> 5;
    const int wm   = (warp & 3) * 32;
    const int wn   = (warp >> 2) * 32;
    const int m0   = blockIdx.y * 128;
    const int n0   = blockIdx.x * 128;
    const uint32_t sbA = smem_u32(dsm);
    const uint32_t sbW = sbA + N_STAGES * HS_TILE;

    if (tid < 128) sbias[tid] = bias[n0 + tid];

    // staging maps: thread -> row tid>>2, 16B chunk (tid&3)
    const int rC = tid >> 2;
    const int kH = (tid & 3) * 8;                 // halves (A) / floats (W)
    const uint32_t dC = (uint32_t)rC * HS_ROW + kH * 2;

    const __half* Ab = A + (size_t)m0 * Kdim;
    const float*  Wb = Wt + (size_t)(n0 + rC) * Kdim + kH;

    const int T = Kdim >> 5;   // BK = 32

    auto issueA = [&](int it) {
        uint32_t st = sbA + (it & (N_STAGES - 1)) * HS_TILE;
        cp_async16(st + dC, Ab + (size_t)rC * Kdim + it * 32 + kH);
        cp_commit();
    };

    const uint32_t a_lm = ((lane & 7) + ((lane >> 3) & 1) * 8) * HS_ROW + ((lane >> 4) & 1) * 16;
    const uint32_t b_lm = ((lane & 7) + ((lane >> 4) & 1) * 8) * HS_ROW + ((lane >> 3) & 1) * 16;

    float acc[2][4][4];
#pragma unroll
    for (int i = 0; i < 2; i++)
#pragma unroll
        for (int j = 0; j < 4; j++)
#pragma unroll
            for (int r = 0; r < 4; r++) acc[i][j][r] = 0.0f;

    // prologue: W(0) into registers, A stages 0..2
    float4 wr0 = *reinterpret_cast<const float4*>(Wb);
    float4 wr1 = *reinterpret_cast<const float4*>(Wb + 4);
#pragma unroll
    for (int i = 0; i < N_STAGES - 1; i++) issueA(i);

    for (int it = 0; it < T; ++it) {
        cp_wait<N_STAGES - 2>();
        // stage W(it) into buffer (it&1)
        *reinterpret_cast<uint4*>(dsm + (N_STAGES + (it & 1)) * HS_TILE + dC) = pack8(wr0, wr1);
        __syncthreads();

        if (it + N_STAGES - 1 < T) issueA(it + N_STAGES - 1);
        else cp_commit();
        if (it + 1 < T) {
            wr0 = *reinterpret_cast<const float4*>(Wb + (it + 1) * 32);
            wr1 = *reinterpret_cast<const float4*>(Wb + (it + 1) * 32 + 4);
        }

        const uint32_t sa  = sbA + (it & (N_STAGES - 1)) * HS_TILE;
        const uint32_t sbm = sbW + (it & 1) * HS_TILE;
#pragma unroll
        for (int kk = 0; kk < 2; kk++) {
            uint32_t af[2][4], bf[2][4];
#pragma unroll
            for (int im = 0; im < 2; im++)
                ldmx4(af[im], sa + (wm + im * 16) * HS_ROW + a_lm + kk * 32);
#pragma unroll
            for (int jn = 0; jn < 2; jn++)
                ldmx4(bf[jn], sbm + (wn + jn * 16) * HS_ROW + b_lm + kk * 32);
#pragma unroll
            for (int im = 0; im < 2; im++)
#pragma unroll
                for (int jn = 0; jn < 2; jn++) {
                    mma_f16(acc[im][2 * jn],     af[im], &bf[jn][0]);
                    mma_f16(acc[im][2 * jn + 1], af[im], &bf[jn][2]);
                }
        }
    }

    const int g = lane >> 2, t = lane & 3;
#pragma unroll
    for (int im = 0; im < 2; im++) {
        int r0 = m0 + wm + im * 16 + g;
#pragma unroll
        for (int in_ = 0; in_ < 4; in_++) {
            int cl = wn + in_ * 8 + t * 2;
            float b0v = sbias[cl], b1v = sbias[cl + 1];
            float v00 = acc[im][in_][0] + b0v;
            float v01 = acc[im][in_][1] + b1v;
            float v10 = acc[im][in_][2] + b0v;
            float v11 = acc[im][in_][3] + b1v;
            if (ACT == ACT_RELU) {
                v00 = fmaxf(v00, 0.0f); v01 = fmaxf(v01, 0.0f);
                v10 = fmaxf(v10, 0.0f); v11 = fmaxf(v11, 0.0f);
            }
            int c = n0 + cl;
            __half2 lo = __floats2half2_rn(v00, v01);
            __half2 hi = __floats2half2_rn(v10, v11);
            *reinterpret_cast<__half2*>(&C[(size_t)r0 * Ndim + c]) = lo;
            *reinterpret_cast<__half2*>(&C[(size_t)(r0 + 8) * Ndim + c]) = hi;
        }
    }
}

// ===================== split-K fp16 GEMM for mulv (atomic accumulate) =====================
#define HS_STAGE (2 * HS_TILE)
#define SM_GEMM_TOTAL (N_STAGES * HS_STAGE)   // 81920 B dynamic

__global__ void __launch_bounds__(512, 2) gemm_splitk_kernel(
    const __half* __restrict__ A, const __half* __restrict__ Wt,
    float* __restrict__ C, int Ndim, int Kstride, int Kchunk)
{
    extern __shared__ __align__(16) uint8_t dsm[];

    const int tid  = threadIdx.x;
    const int lane = tid & 31;
    const int warp = tid >> 5;
    const int wm   = (warp & 3) * 32;
    const int wn   = (warp >> 2) * 32;
    const int m0   = blockIdx.y * 128;
    const int n0   = blockIdx.x * 128;
    const int koff = blockIdx.z * Kchunk;
    const uint32_t sb = smem_u32(dsm);

    const int rC = tid >> 2;
    const int kC = (tid & 3) * 8;
    const uint32_t dC = (uint32_t)rC * HS_ROW + kC * 2;

    const __half* Ab = A  + (size_t)m0 * Kstride + koff;
    const __half* Bb = Wt + (size_t)n0 * Kstride + koff;

    const int T = Kchunk >> 5;

    auto issue = [&](int it) {
        uint32_t st = sb + (it & (N_STAGES - 1)) * HS_STAGE;
        cp_async16(st + dC,           Ab + (size_t)rC * Kstride + it * 32 + kC);
        cp_async16(st + HS_TILE + dC, Bb + (size_t)rC * Kstride + it * 32 + kC);
        cp_commit();
    };

    const uint32_t a_lm = ((lane & 7) + ((lane >> 3) & 1) * 8) * HS_ROW + ((lane >> 4) & 1) * 16;
    const uint32_t b_lm = ((lane & 7) + ((lane >> 4) & 1) * 8) * HS_ROW + ((lane >> 3) & 1) * 16;

    float acc[2][4][4];
#pragma unroll
    for (int i = 0; i < 2; i++)
#pragma unroll
        for (int j = 0; j < 4; j++)
#pragma unroll
            for (int r = 0; r < 4; r++) acc[i][j][r] = 0.0f;

#pragma unroll
    for (int i = 0; i < N_STAGES - 1; i++) issue(i);

    for (int it = 0; it < T; ++it) {
        cp_wait<N_STAGES - 2>();
        __syncthreads();

        if (it + N_STAGES - 1 < T) issue(it + N_STAGES - 1);
        else cp_commit();

        const uint32_t sa  = sb + (it & (N_STAGES - 1)) * HS_STAGE;
        const uint32_t sbm = sa + HS_TILE;
#pragma unroll
        for (int kk = 0; kk < 2; kk++) {
            uint32_t af[2][4], bf[2][4];
#pragma unroll
            for (int im = 0; im < 2; im++)
                ldmx4(af[im], sa + (wm + im * 16) * HS_ROW + a_lm + kk * 32);
#pragma unroll
            for (int jn = 0; jn < 2; jn++)
                ldmx4(bf[jn], sbm + (wn + jn * 16) * HS_ROW + b_lm + kk * 32);
#pragma unroll
            for (int im = 0; im < 2; im++)
#pragma unroll
                for (int jn = 0; jn < 2; jn++) {
                    mma_f16(acc[im][2 * jn],     af[im], &bf[jn][0]);
                    mma_f16(acc[im][2 * jn + 1], af[im], &bf[jn][2]);
                }
        }
    }

    const int g = lane >> 2, t = lane & 3;
#pragma unroll
    for (int im = 0; im < 2; im++) {
        int r0 = m0 + wm + im * 16 + g;
#pragma unroll
        for (int in_ = 0; in_ < 4; in_++) {
            int c = n0 + wn + in_ * 8 + t * 2;
            atomicAdd(&C[(size_t)r0 * Ndim + c],           acc[im][in_][0]);
            atomicAdd(&C[(size_t)r0 * Ndim + c + 1],       acc[im][in_][1]);
            atomicAdd(&C[(size_t)(r0 + 8) * Ndim + c],     acc[im][in_][2]);
            atomicAdd(&C[(size_t)(r0 + 8) * Ndim + c + 1], acc[im][in_][3]);
        }
    }
}

// ===================== reparameterization + mu/logvar output =====================
__global__ void z_kernel(const float* __restrict__ mulv, const float* __restrict__ eps,
                         const float* __restrict__ mu_b, const float* __restrict__ lv_b,
                         float* __restrict__ z, float* __restrict__ out)
{
    int idx = blockIdx.x * 256 + threadIdx.x;
    if (idx >= B_DIM * Z_DIM) return;
    int b = idx >> 6, j = idx & 63;
    float mu = mulv[(size_t)b * 128 + j]      + mu_b[j];
    float lv = mulv[(size_t)b * 128 + 64 + j] + lv_b[j];
    z[idx] = mu + expf(0.5f * lv) * eps[idx];
    out[OFF_MU + idx] = mu;
    out[OFF_LV + idx] = lv;
}

// ===================== fused decoder: fulcon GEMM + block-diag layers + output =======
#define DEC_SMEM (2 * 64 * 132 * 4)    // 67584 B

__global__ void __launch_bounds__(256) decoder_kernel(
    const float* __restrict__ z,
    const float* __restrict__ m_ful_w, const float* __restrict__ m_ful_b,
    const float* __restrict__ m_h_w,   const float* __restrict__ m_h_b,
    const float* __restrict__ m_out_w, const float* __restrict__ m_out_b,
    const float* __restrict__ c_ful_w, const float* __restrict__ c_ful_b,
    const float* __restrict__ c_h_w,   const float* __restrict__ c_h_b,
    const float* __restrict__ c_out_w, const float* __restrict__ c_out_b,
    float* __restrict__ out)
{
    extern __shared__ float ds[];
    float* Zs = ds;               // [64 k][132]
    float* Ws = ds + 64 * 132;    // [64 k][132]
    __shared__ float sfb[128];

    const bool mean = (blockIdx.z == 0);
    const float* fw = mean ? m_ful_w : c_ful_w;
    const float* fb = mean ? m_ful_b : c_ful_b;
    const float* hw = mean ? m_h_w   : c_h_w;
    const float* hb = mean ? m_h_b   : c_h_b;
    const float* ow = mean ? m_out_w : c_out_w;
    const float* ob = mean ? m_out_b : c_out_b;
    const int out_off = mean ? OFF_XREC : OFF_LCOV;

    const int tid = threadIdx.x;
    const int tx  = tid & 15;
    const int ty  = tid >> 4;
    const int n0  = blockIdx.x * 128;
    const int b0  = blockIdx.y * 128;

#pragma unroll
    for (int it = 0; it < 8; it++) {
        int idx = tid + it * 256;
        int row = idx >> 4, kq = (idx & 15) * 4;
        float4 v = *reinterpret_cast<const float4*>(&z[(size_t)(b0 + row) * 64 + kq]);
        Zs[(kq + 0) * 132 + row] = v.x; Zs[(kq + 1) * 132 + row] = v.y;
        Zs[(kq + 2) * 132 + row] = v.z; Zs[(kq + 3) * 132 + row] = v.w;
    }
#pragma unroll
    for (int it = 0; it < 8; it++) {
        int idx = tid + it * 256;
        int row = idx >> 4, kq = (idx & 15) * 4;
        float4 v = *reinterpret_cast<const float4*>(&fw[(size_t)(n0 + row) * 64 + kq]);
        Ws[(kq + 0) * 132 + row] = v.x; Ws[(kq + 1) * 132 + row] = v.y;
        Ws[(kq + 2) * 132 + row] = v.z; Ws[(kq + 3) * 132 + row] = v.w;
    }
    if (tid < 128) sfb[tid] = fb[n0 + tid];
    __syncthreads();

    float acc[8][8];
#pragma unroll
    for (int i = 0; i < 8; i++)
#pragma unroll
        for (int j = 0; j < 8; j++) acc[i][j] = 0.0f;

#pragma unroll 4
    for (int k = 0; k < 64; k++) {
        float ar[8], br[8];
        *reinterpret_cast<float4*>(&ar[0]) = *reinterpret_cast<const float4*>(&Zs[k * 132 + ty * 8]);
        *reinterpret_cast<float4*>(&ar[4]) = *reinterpret_cast<const float4*>(&Zs[k * 132 + ty * 8 + 4]);
        *reinterpret_cast<float4*>(&br[0]) = *reinterpret_cast<const float4*>(&Ws[k * 132 + tx * 8]);
        *reinterpret_cast<float4*>(&br[4]) = *reinterpret_cast<const float4*>(&Ws[k * 132 + tx * 8 + 4]);
#pragma unroll
        for (int i = 0; i < 8; i++)
#pragma unroll
            for (int j = 0; j < 8; j++)
                acc[i][j] = fmaf(ar[i], br[j], acc[i][j]);
    }
#pragma unroll
    for (int i = 0; i < 8; i++)
#pragma unroll
        for (int j = 0; j < 8; j++)
            acc[i][j] = sigm(acc[i][j] + sfb[tx * 8 + j]);

    __syncthreads();
    float* Os = ds;    // [128 b][64 m]

#pragma unroll
    for (int jj = 0; jj < 4; jj++) {
        int m = (n0 >> 1) + tx * 4 + jj;
        float4 w0 = *reinterpret_cast<const float4*>(&hw[(size_t)m * 4]);
        float4 w1 = *reinterpret_cast<const float4*>(&hw[((size_t)M_DIM + m) * 4]);
        float b00 = hb[2 * m],          b01 = hb[2 * m + 1];
        float b10 = hb[H_DIM + 2 * m],  b11 = hb[H_DIM + 2 * m + 1];
        float2 owv = *reinterpret_cast<const float2*>(&ow[2 * m]);
        float obv = ob[m];
#pragma unroll
        for (int i = 0; i < 8; i++) {
            float a0 = acc[i][2 * jj], a1 = acc[i][2 * jj + 1];
            float t0 = sigm(fmaf(a0, w0.x, fmaf(a1, w0.y, b00)));
            float t1 = sigm(fmaf(a0, w0.z, fmaf(a1, w0.w, b01)));
            a0 = sigm(fmaf(t0, w1.x, fmaf(t1, w1.y, b10)));
            a1 = sigm(fmaf(t0, w1.z, fmaf(t1, w1.w, b11)));
            Os[(ty * 8 + i) * 64 + tx * 4 + jj] = fmaf(a0, owv.x, fmaf(a1, owv.y, obv));
        }
    }
    __syncthreads();

#pragma unroll
    for (int it = 0; it < 8; it++) {
        int idx = tid + it * 256;
        int row = idx >> 4, mq = (idx & 15) * 4;
        float4 v = *reinterpret_cast<const float4*>(&Os[row * 64 + mq]);
        *reinterpret_cast<float4*>(&out[out_off + (size_t)(b0 + row) * M_DIM + (n0 >> 1) + mq]) = v;
    }
}

// ===================== launch =====================
extern "C" void kernel_launch(void* const* d_in, const int* in_sizes, int n_in,
                              void* d_out, int out_size)
{
    const float* x        = (const float*)d_in[0];
    const float* eps      = (const float*)d_in[1];
    const float* enc1_w   = (const float*)d_in[2];
    const float* enc1_b   = (const float*)d_in[3];
    const float* enc2_w   = (const float*)d_in[4];
    const float* enc2_b   = (const float*)d_in[5];
    const float* mu_w     = (const float*)d_in[6];
    const float* mu_b     = (const float*)d_in[7];
    const float* lv_w     = (const float*)d_in[8];
    const float* lv_b     = (const float*)d_in[9];
    const float* m_ful_w  = (const float*)d_in[10];
    const float* m_ful_b  = (const float*)d_in[11];
    const float* m_h_w    = (const float*)d_in[12];
    const float* m_h_b    = (const float*)d_in[13];
    const float* m_out_w  = (const float*)d_in[14];
    const float* m_out_b  = (const float*)d_in[15];
    const float* c_ful_w  = (const float*)d_in[16];
    const float* c_ful_b  = (const float*)d_in[17];
    const float* c_h_w    = (const float*)d_in[18];
    const float* c_h_b    = (const float*)d_in[19];
    const float* c_out_w  = (const float*)d_in[20];
    const float* c_out_b  = (const float*)d_in[21];
    float* out = (float*)d_out;

    __half *xh, *wch, *h1h, *h2h;
    float *mulv, *z;
    cudaGetSymbolAddress((void**)&xh,   g_xh);
    cudaGetSymbolAddress((void**)&wch,  g_wch);
    cudaGetSymbolAddress((void**)&h1h,  g_h1h);
    cudaGetSymbolAddress((void**)&h2h,  g_h2h);
    cudaGetSymbolAddress((void**)&mulv, g_mulv);
    cudaGetSymbolAddress((void**)&z,    g_z);

    cudaFuncSetAttribute((const void*)gemm_h16_wf32_kernel<ACT_RELU>,
                         cudaFuncAttributeMaxDynamicSharedMemorySize, WF_SMEM);
    cudaFuncSetAttribute((const void*)gemm_splitk_kernel,
                         cudaFuncAttributeMaxDynamicSharedMemorySize, SM_GEMM_TOTAL);
    cudaFuncSetAttribute((const void*)decoder_kernel,
                         cudaFuncAttributeMaxDynamicSharedMemorySize, DEC_SMEM);

    // ---- prep: fp32 -> fp16 for x and mu_w|lv_w only (~20 MB) ----
    f2hS_kernel<<<(NS8 + 255) / 256, 256>>>(x, mu_w, lv_w, xh, wch);

    // ---- encoder GEMMs: W converted fp32->fp16 inside the kernel ----
    dim3 g1(M_DIM / 128, B_DIM / 128);
    gemm_h16_wf32_kernel<ACT_RELU><<<g1, 512, WF_SMEM>>>(
        xh,  enc1_w, enc1_b, h1h, M_DIM, M_DIM);
    gemm_h16_wf32_kernel<ACT_RELU><<<g1, 512, WF_SMEM>>>(
        h1h, enc2_w, enc2_b, h2h, M_DIM, M_DIM);

    // ---- mu / logvar projection: split-K tensor GEMM (atomic accumulate) ----
    cudaMemsetAsync(mulv, 0, B_DIM * 128 * sizeof(float), 0);
    dim3 g2(1, B_DIM / 128, 16);   // N=128 tile, 8 M-tiles, 16 K-chunks of 256
    gemm_splitk_kernel<<<g2, 512, SM_GEMM_TOTAL>>>(h2h, wch, mulv, 128, M_DIM, 256);

    z_kernel<<<(B_DIM * Z_DIM + 255) / 256, 256>>>(mulv, eps, mu_b, lv_b, z, out);

    // ---- fused decoder (both branches) ----
    dim3 g3(H_DIM / 128, B_DIM / 128, 2);
    decoder_kernel<<<g3, 256, DEC_SMEM>>>(
        z,
        m_ful_w, m_ful_b, m_h_w, m_h_b, m_out_w, m_out_b,
        c_ful_w, c_ful_b, c_h_w, c_h_b, c_out_w, c_out_b,
        out);
}

// round 13
// speedup vs baseline: 1.2500x; 1.2500x over previous
#include <cuda_runtime.h>
#include <cuda_fp16.h>
#include <cstdint>
#include <cstddef>

// Problem dims (fixed)
#define B_DIM 1024
#define M_DIM 4096
#define W_DIM 2
#define L_DIM 2
#define Z_DIM 64
#define H_DIM 8192   // M*W

// Output layout: x_recon [B*M], logcov [B*M], mu [B*Z], logvar [B*Z]
#define OFF_XREC  0
#define OFF_LCOV  (B_DIM * M_DIM)
#define OFF_MU    (2 * B_DIM * M_DIM)
#define OFF_LV    (2 * B_DIM * M_DIM + B_DIM * Z_DIM)

// -------- scratch (no allocations allowed; __device__ globals) --------
__device__ __half g_xh  [B_DIM * M_DIM];   // x in fp16
__device__ __half g_w1h [M_DIM * M_DIM];   // enc1_w in fp16
__device__ __half g_w2h [M_DIM * M_DIM];   // enc2_w in fp16
__device__ __half g_wch [128 * M_DIM];     // concat(mu_w, lv_w) in fp16
__device__ __half g_h1h [B_DIM * M_DIM];   // encoder layer-1 out (fp16)
__device__ __half g_h2h [B_DIM * M_DIM];   // encoder layer-2 out (fp16)
__device__ float  g_mulv[B_DIM * 128];
__device__ float  g_z[B_DIM * Z_DIM];

__device__ __forceinline__ float sigm(float x) { return 1.0f / (1.0f + expf(-x)); }

// ===================== merged fp32 -> fp16 conversion =====================
#define NX8 (B_DIM * M_DIM / 8)
#define NW8 (M_DIM * M_DIM / 8)
#define NC8 (64 * M_DIM / 8)
#define NTOT8 (NX8 + 2 * NW8 + 2 * NC8)

__device__ __forceinline__ void cvt8(const float* __restrict__ in, __half* __restrict__ out, int j) {
    const float4* p = reinterpret_cast<const float4*>(in) + 2 * (size_t)j;
    float4 a = p[0], b = p[1];
    __half2 h0 = __floats2half2_rn(a.x, a.y);
    __half2 h1 = __floats2half2_rn(a.z, a.w);
    __half2 h2 = __floats2half2_rn(b.x, b.y);
    __half2 h3 = __floats2half2_rn(b.z, b.w);
    uint4 u;
    u.x = *reinterpret_cast<uint32_t*>(&h0);
    u.y = *reinterpret_cast<uint32_t*>(&h1);
    u.z = *reinterpret_cast<uint32_t*>(&h2);
    u.w = *reinterpret_cast<uint32_t*>(&h3);
    reinterpret_cast<uint4*>(out)[j] = u;
}

__global__ void __launch_bounds__(256) f2h5_kernel(
    const float* __restrict__ x,  const float* __restrict__ w1,
    const float* __restrict__ w2, const float* __restrict__ muw,
    const float* __restrict__ lvw,
    __half* __restrict__ xh, __half* __restrict__ w1h,
    __half* __restrict__ w2h, __half* __restrict__ wch)
{
    int i = blockIdx.x * 256 + threadIdx.x;
    if (i < NX8)                      cvt8(x,   xh,  i);
    else if (i < NX8 + NW8)           cvt8(w1,  w1h, i - NX8);
    else if (i < NX8 + 2 * NW8)       cvt8(w2,  w2h, i - NX8 - NW8);
    else if (i < NX8 + 2 * NW8 + NC8) cvt8(muw, wch, i - NX8 - 2 * NW8);
    else if (i < NTOT8)               cvt8(lvw, wch + 64 * M_DIM, i - NX8 - 2 * NW8 - NC8);
}

// ===================== common GEMM helpers =====================
__device__ __forceinline__ uint32_t smem_u32(const void* p) {
    uint32_t a;
    asm("{ .reg .u64 t; cvta.to.shared.u64 t, %1; cvt.u32.u64 %0, t; }" : "=r"(a) : "l"(p));
    return a;
}
__device__ __forceinline__ void ldmx4(uint32_t* r, uint32_t addr) {
    asm volatile("ldmatrix.sync.aligned.m8n8.x4.shared.b16 {%0,%1,%2,%3}, [%4];"
                 : "=r"(r[0]), "=r"(r[1]), "=r"(r[2]), "=r"(r[3]) : "r"(addr));
}
__device__ __forceinline__ void mma_f16(float* d, const uint32_t* a, const uint32_t* b) {
    asm volatile(
        "mma.sync.aligned.m16n8k16.row.col.f32.f16.f16.f32 "
        "{%0,%1,%2,%3}, {%4,%5,%6,%7}, {%8,%9}, {%0,%1,%2,%3};\n"
        : "+f"(d[0]), "+f"(d[1]), "+f"(d[2]), "+f"(d[3])
        : "r"(a[0]), "r"(a[1]), "r"(a[2]), "r"(a[3]), "r"(b[0]), "r"(b[1]));
}
__device__ __forceinline__ void cp_async16(uint32_t smem_addr, const void* gptr) {
    asm volatile("cp.async.cg.shared.global [%0], [%1], 16;\n" :: "r"(smem_addr), "l"(gptr));
}
__device__ __forceinline__ void cp_commit() { asm volatile("cp.async.commit_group;\n"); }
template <int N> __device__ __forceinline__ void cp_wait() {
    asm volatile("cp.async.wait_group %0;\n" :: "n"(N));
}

// ============ balanced encoder GEMM: 64x64 tiles, grid 1024, 7 CTAs/SM ============
// C(fp16) = relu(A * W^T + bias); A,W fp16 K-contiguous. 128 threads (4 warps,
// 32x32 warp tiles), BK=32, 3-stage cp.async ring.
#define G64_ROW   80                 // bytes/row (32 halves + pad)
#define G64_TILE  (64 * G64_ROW)     // 5120 B
#define G64_STAGE (2 * G64_TILE)     // 10240 B (A + B)
#define G64_NST   3
#define G64_SMEM  (G64_NST * G64_STAGE)   // 30720 B dynamic -> 7 CTAs/SM

__global__ void __launch_bounds__(128) gemm64_kernel(
    const __half* __restrict__ A, const __half* __restrict__ Wt,
    const float* __restrict__ bias, __half* __restrict__ C,
    int Ndim, int Kdim)
{
    extern __shared__ __align__(16) uint8_t dsm[];
    __shared__ float sbias[64];

    const int tid  = threadIdx.x;
    const int lane = tid & 31;
    const int warp = tid >> 5;            // 0..3
    const int wm   = (warp & 1) * 32;
    const int wn   = (warp >> 1) * 32;
    const int m0   = blockIdx.y * 64;
    const int n0   = blockIdx.x * 64;
    const uint32_t sb = smem_u32(dsm);

    if (tid < 64) sbias[tid] = bias[n0 + tid];

    // cp.async: each thread loads one 32B segment (2x16B) per tile per stage.
    const int rA = tid >> 1;              // row 0..63
    const int kA = (tid & 1) * 16;        // halves: 0 or 16
    const uint32_t dA = (uint32_t)rA * G64_ROW + kA * 2;

    const __half* Ab = A  + (size_t)m0 * Kdim;
    const __half* Bb = Wt + (size_t)n0 * Kdim;

    const int T = Kdim >> 5;   // BK = 32

    auto issue = [&](int it) {
        uint32_t st = sb + (it % G64_NST) * G64_STAGE;
        const __half* Ap = Ab + (size_t)rA * Kdim + it * 32 + kA;
        const __half* Bp = Bb + (size_t)rA * Kdim + it * 32 + kA;
        cp_async16(st + dA,                  Ap);
        cp_async16(st + dA + 16,             Ap + 8);
        cp_async16(st + G64_TILE + dA,       Bp);
        cp_async16(st + G64_TILE + dA + 16,  Bp + 8);
        cp_commit();
    };

    const uint32_t a_lm = ((lane & 7) + ((lane >> 3) & 1) * 8) * G64_ROW + ((lane >> 4) & 1) * 16;
    const uint32_t b_lm = ((lane & 7) + ((lane >> 4) & 1) * 8) * G64_ROW + ((lane >> 3) & 1) * 16;

    float acc[2][4][4];
#pragma unroll
    for (int i = 0; i < 2; i++)
#pragma unroll
        for (int j = 0; j < 4; j++)
#pragma unroll
            for (int r = 0; r < 4; r++) acc[i][j][r] = 0.0f;

    issue(0);
    issue(1);

    for (int it = 0; it < T; ++it) {
        cp_wait<1>();
        __syncthreads();

        if (it + 2 < T) issue(it + 2);
        else cp_commit();    // uniform group count

        const uint32_t sa  = sb + (it % G64_NST) * G64_STAGE;
        const uint32_t sbm = sa + G64_TILE;
#pragma unroll
        for (int kk = 0; kk < 2; kk++) {
            uint32_t af[2][4], bf[2][4];
#pragma unroll
            for (int im = 0; im < 2; im++)
                ldmx4(af[im], sa + (wm + im * 16) * G64_ROW + a_lm + kk * 32);
#pragma unroll
            for (int jn = 0; jn < 2; jn++)
                ldmx4(bf[jn], sbm + (wn + jn * 16) * G64_ROW + b_lm + kk * 32);
#pragma unroll
            for (int im = 0; im < 2; im++)
#pragma unroll
                for (int jn = 0; jn < 2; jn++) {
                    mma_f16(acc[im][2 * jn],     af[im], &bf[jn][0]);
                    mma_f16(acc[im][2 * jn + 1], af[im], &bf[jn][2]);
                }
        }
        __syncthreads();
    }

    const int g = lane >> 2, t = lane & 3;
#pragma unroll
    for (int im = 0; im < 2; im++) {
        int r0 = m0 + wm + im * 16 + g;
#pragma unroll
        for (int in_ = 0; in_ < 4; in_++) {
            int cl = wn + in_ * 8 + t * 2;
            float b0v = sbias[cl], b1v = sbias[cl + 1];
            float v00 = fmaxf(acc[im][in_][0] + b0v, 0.0f);
            float v01 = fmaxf(acc[im][in_][1] + b1v, 0.0f);
            float v10 = fmaxf(acc[im][in_][2] + b0v, 0.0f);
            float v11 = fmaxf(acc[im][in_][3] + b1v, 0.0f);
            int c = n0 + cl;
            __half2 lo = __floats2half2_rn(v00, v01);
            __half2 hi = __floats2half2_rn(v10, v11);
            *reinterpret_cast<__half2*>(&C[(size_t)r0 * Ndim + c]) = lo;
            *reinterpret_cast<__half2*>(&C[(size_t)(r0 + 8) * Ndim + c]) = hi;
        }
    }
}

// ===================== split-K fp16 GEMM for mulv (atomic accumulate) =====================
#define HS_ROW   80
#define HS_TILE  (128 * HS_ROW)
#define HS_STAGE (2 * HS_TILE)
#define N_STAGES 4
#define SM_GEMM_TOTAL (N_STAGES * HS_STAGE)   // 81920 B dynamic

__global__ void __launch_bounds__(512, 2) gemm_splitk_kernel(
    const __half* __restrict__ A, const __half* __restrict__ Wt,
    float* __restrict__ C, int Ndim, int Kstride, int Kchunk)
{
    extern __shared__ __align__(16) uint8_t dsm[];

    const int tid  = threadIdx.x;
    const int lane = tid & 31;
    const int warp = tid >> 5;
    const int wm   = (warp & 3) * 32;
    const int wn   = (warp >> 2) * 32;
    const int m0   = blockIdx.y * 128;
    const int n0   = blockIdx.x * 128;
    const int koff = blockIdx.z * Kchunk;
    const uint32_t sb = smem_u32(dsm);

    const int rC = tid >> 2;
    const int kC = (tid & 3) * 8;
    const uint32_t dC = (uint32_t)rC * HS_ROW + kC * 2;

    const __half* Ab = A  + (size_t)m0 * Kstride + koff;
    const __half* Bb = Wt + (size_t)n0 * Kstride + koff;

    const int T = Kchunk >> 5;

    auto issue = [&](int it) {
        uint32_t st = sb + (it & (N_STAGES - 1)) * HS_STAGE;
        cp_async16(st + dC,           Ab + (size_t)rC * Kstride + it * 32 + kC);
        cp_async16(st + HS_TILE + dC, Bb + (size_t)rC * Kstride + it * 32 + kC);
        cp_commit();
    };

    const uint32_t a_lm = ((lane & 7) + ((lane >> 3) & 1) * 8) * HS_ROW + ((lane >> 4) & 1) * 16;
    const uint32_t b_lm = ((lane & 7) + ((lane >> 4) & 1) * 8) * HS_ROW + ((lane >> 3) & 1) * 16;

    float acc[2][4][4];
#pragma unroll
    for (int i = 0; i < 2; i++)
#pragma unroll
        for (int j = 0; j < 4; j++)
#pragma unroll
            for (int r = 0; r < 4; r++) acc[i][j][r] = 0.0f;

#pragma unroll
    for (int i = 0; i < N_STAGES - 1; i++) issue(i);

    for (int it = 0; it < T; ++it) {
        cp_wait<N_STAGES - 2>();
        __syncthreads();

        if (it + N_STAGES - 1 < T) issue(it + N_STAGES - 1);
        else cp_commit();

        const uint32_t sa  = sb + (it & (N_STAGES - 1)) * HS_STAGE;
        const uint32_t sbm = sa + HS_TILE;
#pragma unroll
        for (int kk = 0; kk < 2; kk++) {
            uint32_t af[2][4], bf[2][4];
#pragma unroll
            for (int im = 0; im < 2; im++)
                ldmx4(af[im], sa + (wm + im * 16) * HS_ROW + a_lm + kk * 32);
#pragma unroll
            for (int jn = 0; jn < 2; jn++)
                ldmx4(bf[jn], sbm + (wn + jn * 16) * HS_ROW + b_lm + kk * 32);
#pragma unroll
            for (int im = 0; im < 2; im++)
#pragma unroll
                for (int jn = 0; jn < 2; jn++) {
                    mma_f16(acc[im][2 * jn],     af[im], &bf[jn][0]);
                    mma_f16(acc[im][2 * jn + 1], af[im], &bf[jn][2]);
                }
        }
    }

    const int g = lane >> 2, t = lane & 3;
#pragma unroll
    for (int im = 0; im < 2; im++) {
        int r0 = m0 + wm + im * 16 + g;
#pragma unroll
        for (int in_ = 0; in_ < 4; in_++) {
            int c = n0 + wn + in_ * 8 + t * 2;
            atomicAdd(&C[(size_t)r0 * Ndim + c],           acc[im][in_][0]);
            atomicAdd(&C[(size_t)r0 * Ndim + c + 1],       acc[im][in_][1]);
            atomicAdd(&C[(size_t)(r0 + 8) * Ndim + c],     acc[im][in_][2]);
            atomicAdd(&C[(size_t)(r0 + 8) * Ndim + c + 1], acc[im][in_][3]);
        }
    }
}

// ===================== reparameterization + mu/logvar output =====================
__global__ void z_kernel(const float* __restrict__ mulv, const float* __restrict__ eps,
                         const float* __restrict__ mu_b, const float* __restrict__ lv_b,
                         float* __restrict__ z, float* __restrict__ out)
{
    int idx = blockIdx.x * 256 + threadIdx.x;
    if (idx >= B_DIM * Z_DIM) return;
    int b = idx >> 6, j = idx & 63;
    float mu = mulv[(size_t)b * 128 + j]      + mu_b[j];
    float lv = mulv[(size_t)b * 128 + 64 + j] + lv_b[j];
    z[idx] = mu + expf(0.5f * lv) * eps[idx];
    out[OFF_MU + idx] = mu;
    out[OFF_LV + idx] = lv;
}

// ===================== fused decoder: fulcon GEMM + block-diag layers + output =======
#define DEC_SMEM (2 * 64 * 132 * 4)    // 67584 B

__global__ void __launch_bounds__(256) decoder_kernel(
    const float* __restrict__ z,
    const float* __restrict__ m_ful_w, const float* __restrict__ m_ful_b,
    const float* __restrict__ m_h_w,   const float* __restrict__ m_h_b,
    const float* __restrict__ m_out_w, const float* __restrict__ m_out_b,
    const float* __restrict__ c_ful_w, const float* __restrict__ c_ful_b,
    const float* __restrict__ c_h_w,   const float* __restrict__ c_h_b,
    const float* __restrict__ c_out_w, const float* __restrict__ c_out_b,
    float* __restrict__ out)
{
    extern __shared__ float ds[];
    float* Zs = ds;               // [64 k][132]
    float* Ws = ds + 64 * 132;    // [64 k][132]
    __shared__ float sfb[128];

    const bool mean = (blockIdx.z == 0);
    const float* fw = mean ? m_ful_w : c_ful_w;
    const float* fb = mean ? m_ful_b : c_ful_b;
    const float* hw = mean ? m_h_w   : c_h_w;
    const float* hb = mean ? m_h_b   : c_h_b;
    const float* ow = mean ? m_out_w : c_out_w;
    const float* ob = mean ? m_out_b : c_out_b;
    const int out_off = mean ? OFF_XREC : OFF_LCOV;

    const int tid = threadIdx.x;
    const int tx  = tid & 15;
    const int ty  = tid >> 4;
    const int n0  = blockIdx.x * 128;
    const int b0  = blockIdx.y * 128;

#pragma unroll
    for (int it = 0; it < 8; it++) {
        int idx = tid + it * 256;
        int row = idx >> 4, kq = (idx & 15) * 4;
        float4 v = *reinterpret_cast<const float4*>(&z[(size_t)(b0 + row) * 64 + kq]);
        Zs[(kq + 0) * 132 + row] = v.x; Zs[(kq + 1) * 132 + row] = v.y;
        Zs[(kq + 2) * 132 + row] = v.z; Zs[(kq + 3) * 132 + row] = v.w;
    }
#pragma unroll
    for (int it = 0; it < 8; it++) {
        int idx = tid + it * 256;
        int row = idx >> 4, kq = (idx & 15) * 4;
        float4 v = *reinterpret_cast<const float4*>(&fw[(size_t)(n0 + row) * 64 + kq]);
        Ws[(kq + 0) * 132 + row] = v.x; Ws[(kq + 1) * 132 + row] = v.y;
        Ws[(kq + 2) * 132 + row] = v.z; Ws[(kq + 3) * 132 + row] = v.w;
    }
    if (tid < 128) sfb[tid] = fb[n0 + tid];
    __syncthreads();

    float acc[8][8];
#pragma unroll
    for (int i = 0; i < 8; i++)
#pragma unroll
        for (int j = 0; j < 8; j++) acc[i][j] = 0.0f;

#pragma unroll 4
    for (int k = 0; k < 64; k++) {
        float ar[8], br[8];
        *reinterpret_cast<float4*>(&ar[0]) = *reinterpret_cast<const float4*>(&Zs[k * 132 + ty * 8]);
        *reinterpret_cast<float4*>(&ar[4]) = *reinterpret_cast<const float4*>(&Zs[k * 132 + ty * 8 + 4]);
        *reinterpret_cast<float4*>(&br[0]) = *reinterpret_cast<const float4*>(&Ws[k * 132 + tx * 8]);
        *reinterpret_cast<float4*>(&br[4]) = *reinterpret_cast<const float4*>(&Ws[k * 132 + tx * 8 + 4]);
#pragma unroll
        for (int i = 0; i < 8; i++)
#pragma unroll
            for (int j = 0; j < 8; j++)
                acc[i][j] = fmaf(ar[i], br[j], acc[i][j]);
    }
#pragma unroll
    for (int i = 0; i < 8; i++)
#pragma unroll
        for (int j = 0; j < 8; j++)
            acc[i][j] = sigm(acc[i][j] + sfb[tx * 8 + j]);

    __syncthreads();
    float* Os = ds;    // [128 b][64 m]

#pragma unroll
    for (int jj = 0; jj < 4; jj++) {
        int m = (n0 >> 1) + tx * 4 + jj;
        float4 w0 = *reinterpret_cast<const float4*>(&hw[(size_t)m * 4]);
        float4 w1 = *reinterpret_cast<const float4*>(&hw[((size_t)M_DIM + m) * 4]);
        float b00 = hb[2 * m],          b01 = hb[2 * m + 1];
        float b10 = hb[H_DIM + 2 * m],  b11 = hb[H_DIM + 2 * m + 1];
        float2 owv = *reinterpret_cast<const float2*>(&ow[2 * m]);
        float obv = ob[m];
#pragma unroll
        for (int i = 0; i < 8; i++) {
            float a0 = acc[i][2 * jj], a1 = acc[i][2 * jj + 1];
            float t0 = sigm(fmaf(a0, w0.x, fmaf(a1, w0.y, b00)));
            float t1 = sigm(fmaf(a0, w0.z, fmaf(a1, w0.w, b01)));
            a0 = sigm(fmaf(t0, w1.x, fmaf(t1, w1.y, b10)));
            a1 = sigm(fmaf(t0, w1.z, fmaf(t1, w1.w, b11)));
            Os[(ty * 8 + i) * 64 + tx * 4 + jj] = fmaf(a0, owv.x, fmaf(a1, owv.y, obv));
        }
    }
    __syncthreads();

#pragma unroll
    for (int it = 0; it < 8; it++) {
        int idx = tid + it * 256;
        int row = idx >> 4, mq = (idx & 15) * 4;
        float4 v = *reinterpret_cast<const float4*>(&Os[row * 64 + mq]);
        *reinterpret_cast<float4*>(&out[out_off + (size_t)(b0 + row) * M_DIM + (n0 >> 1) + mq]) = v;
    }
}

// ===================== launch =====================
extern "C" void kernel_launch(void* const* d_in, const int* in_sizes, int n_in,
                              void* d_out, int out_size)
{
    const float* x        = (const float*)d_in[0];
    const float* eps      = (const float*)d_in[1];
    const float* enc1_w   = (const float*)d_in[2];
    const float* enc1_b   = (const float*)d_in[3];
    const float* enc2_w   = (const float*)d_in[4];
    const float* enc2_b   = (const float*)d_in[5];
    const float* mu_w     = (const float*)d_in[6];
    const float* mu_b     = (const float*)d_in[7];
    const float* lv_w     = (const float*)d_in[8];
    const float* lv_b     = (const float*)d_in[9];
    const float* m_ful_w  = (const float*)d_in[10];
    const float* m_ful_b  = (const float*)d_in[11];
    const float* m_h_w    = (const float*)d_in[12];
    const float* m_h_b    = (const float*)d_in[13];
    const float* m_out_w  = (const float*)d_in[14];
    const float* m_out_b  = (const float*)d_in[15];
    const float* c_ful_w  = (const float*)d_in[16];
    const float* c_ful_b  = (const float*)d_in[17];
    const float* c_h_w    = (const float*)d_in[18];
    const float* c_h_b    = (const float*)d_in[19];
    const float* c_out_w  = (const float*)d_in[20];
    const float* c_out_b  = (const float*)d_in[21];
    float* out = (float*)d_out;

    __half *xh, *w1h, *w2h, *wch, *h1h, *h2h;
    float *mulv, *z;
    cudaGetSymbolAddress((void**)&xh,   g_xh);
    cudaGetSymbolAddress((void**)&w1h,  g_w1h);
    cudaGetSymbolAddress((void**)&w2h,  g_w2h);
    cudaGetSymbolAddress((void**)&wch,  g_wch);
    cudaGetSymbolAddress((void**)&h1h,  g_h1h);
    cudaGetSymbolAddress((void**)&h2h,  g_h2h);
    cudaGetSymbolAddress((void**)&mulv, g_mulv);
    cudaGetSymbolAddress((void**)&z,    g_z);

    cudaFuncSetAttribute((const void*)gemm64_kernel,
                         cudaFuncAttributeMaxDynamicSharedMemorySize, G64_SMEM);
    cudaFuncSetAttribute((const void*)gemm_splitk_kernel,
                         cudaFuncAttributeMaxDynamicSharedMemorySize, SM_GEMM_TOTAL);
    cudaFuncSetAttribute((const void*)decoder_kernel,
                         cudaFuncAttributeMaxDynamicSharedMemorySize, DEC_SMEM);

    // ---- prep: fp32 -> fp16 (x, enc1_w, enc2_w, mu_w|lv_w) in one launch ----
    f2h5_kernel<<<(NTOT8 + 255) / 256, 256>>>(x, enc1_w, enc2_w, mu_w, lv_w,
                                              xh, w1h, w2h, wch);

    // ---- encoder GEMMs: 64x64 tiles, grid 1024 (wave-balanced) ----
    dim3 g1(M_DIM / 64, B_DIM / 64);   // (64, 16) = 1024 CTAs
    gemm64_kernel<<<g1, 128, G64_SMEM>>>(xh,  w1h, enc1_b, h1h, M_DIM, M_DIM);
    gemm64_kernel<<<g1, 128, G64_SMEM>>>(h1h, w2h, enc2_b, h2h, M_DIM, M_DIM);

    // ---- mu / logvar projection: split-K tensor GEMM (atomic accumulate) ----
    cudaMemsetAsync(mulv, 0, B_DIM * 128 * sizeof(float), 0);
    dim3 g2(1, B_DIM / 128, 16);   // N=128 tile, 8 M-tiles, 16 K-chunks of 256
    gemm_splitk_kernel<<<g2, 512, SM_GEMM_TOTAL>>>(h2h, wch, mulv, 128, M_DIM, 256);

    z_kernel<<<(B_DIM * Z_DIM + 255) / 256, 256>>>(mulv, eps, mu_b, lv_b, z, out);

    // ---- fused decoder (both branches) ----
    dim3 g3(H_DIM / 128, B_DIM / 128, 2);
    decoder_kernel<<<g3, 256, DEC_SMEM>>>(
        z,
        m_ful_w, m_ful_b, m_h_w, m_h_b, m_out_w, m_out_b,
        c_ful_w, c_ful_b, c_h_w, c_h_b, c_out_w, c_out_b,
        out);
}

// round 14
// speedup vs baseline: 1.3172x; 1.0537x over previous
#include <cuda_runtime.h>
#include <cuda_fp16.h>
#include <cstdint>
#include <cstddef>

// Problem dims (fixed)
#define B_DIM 1024
#define M_DIM 4096
#define W_DIM 2
#define L_DIM 2
#define Z_DIM 64
#define H_DIM 8192   // M*W

// Output layout: x_recon [B*M], logcov [B*M], mu [B*Z], logvar [B*Z]
#define OFF_XREC  0
#define OFF_LCOV  (B_DIM * M_DIM)
#define OFF_MU    (2 * B_DIM * M_DIM)
#define OFF_LV    (2 * B_DIM * M_DIM + B_DIM * Z_DIM)

// -------- scratch (no allocations allowed; __device__ globals) --------
__device__ __half g_wch [128 * M_DIM];     // concat(mu_w, lv_w) in fp16
__device__ __half g_h1h [B_DIM * M_DIM];   // encoder layer-1 out (fp16)
__device__ __half g_h2h [B_DIM * M_DIM];   // encoder layer-2 out (fp16)
__device__ float  g_mulv[B_DIM * 128];
__device__ float  g_z[B_DIM * Z_DIM];

__device__ __forceinline__ float sigm(float x) { return 1.0f / (1.0f + expf(-x)); }

#define ACT_RELU 1

// ===================== tiny prep: mu_w|lv_w -> fp16 concat (4 MB) =====================
#define NC8 (64 * M_DIM / 8)

__global__ void __launch_bounds__(256) f2hC_kernel(
    const float* __restrict__ muw, const float* __restrict__ lvw,
    __half* __restrict__ wch)
{
    int i = blockIdx.x * 256 + threadIdx.x;
    const float* in; __half* out; int j;
    if (i < NC8)          { in = muw; out = wch; j = i; }
    else if (i < 2 * NC8) { in = lvw; out = wch + 64 * M_DIM; j = i - NC8; }
    else return;
    const float4* p = reinterpret_cast<const float4*>(in) + 2 * (size_t)j;
    float4 a = p[0], b = p[1];
    __half2 h0 = __floats2half2_rn(a.x, a.y);
    __half2 h1 = __floats2half2_rn(a.z, a.w);
    __half2 h2 = __floats2half2_rn(b.x, b.y);
    __half2 h3 = __floats2half2_rn(b.z, b.w);
    uint4 u;
    u.x = *reinterpret_cast<uint32_t*>(&h0);
    u.y = *reinterpret_cast<uint32_t*>(&h1);
    u.z = *reinterpret_cast<uint32_t*>(&h2);
    u.w = *reinterpret_cast<uint32_t*>(&h3);
    reinterpret_cast<uint4*>(out)[j] = u;
}

// ===================== common helpers =====================
__device__ __forceinline__ uint32_t smem_u32(const void* p) {
    uint32_t a;
    asm("{ .reg .u64 t; cvta.to.shared.u64 t, %1; cvt.u32.u64 %0, t; }" : "=r"(a) : "l"(p));
    return a;
}
__device__ __forceinline__ void ldmx4(uint32_t* r, uint32_t addr) {
    asm volatile("ldmatrix.sync.aligned.m8n8.x4.shared.b16 {%0,%1,%2,%3}, [%4];"
                 : "=r"(r[0]), "=r"(r[1]), "=r"(r[2]), "=r"(r[3]) : "r"(addr));
}
__device__ __forceinline__ void ldmx2(uint32_t* r, uint32_t addr) {
    asm volatile("ldmatrix.sync.aligned.m8n8.x2.shared.b16 {%0,%1}, [%2];"
                 : "=r"(r[0]), "=r"(r[1]) : "r"(addr));
}
__device__ __forceinline__ void mma_f16(float* d, const uint32_t* a, const uint32_t* b) {
    asm volatile(
        "mma.sync.aligned.m16n8k16.row.col.f32.f16.f16.f32 "
        "{%0,%1,%2,%3}, {%4,%5,%6,%7}, {%8,%9}, {%0,%1,%2,%3};\n"
        : "+f"(d[0]), "+f"(d[1]), "+f"(d[2]), "+f"(d[3])
        : "r"(a[0]), "r"(a[1]), "r"(a[2]), "r"(a[3]), "r"(b[0]), "r"(b[1]));
}
__device__ __forceinline__ void cp_async16(uint32_t smem_addr, const void* gptr) {
    asm volatile("cp.async.cg.shared.global [%0], [%1], 16;\n" :: "r"(smem_addr), "l"(gptr));
}
__device__ __forceinline__ void cp_commit() { asm volatile("cp.async.commit_group;\n"); }
template <int N> __device__ __forceinline__ void cp_wait() {
    asm volatile("cp.async.wait_group %0;\n" :: "n"(N));
}
__device__ __forceinline__ uint32_t pack_h2(float lo, float hi) {
    __half2 h = __floats2half2_rn(lo, hi);
    return *reinterpret_cast<uint32_t*>(&h);
}

// ===================== round-4 GEMM: in-loop fp32->fp16 conversion =====================
// C = act(A * W^T + bias); A fp32 or fp16 [Mrows,K], W fp32 [N,K]. CTA 128x128,
// BK=32, 256 threads, 8 warps (64x32 warp tiles), 2-stage register-prefetch staging.
#define HS_ROW 80                 // bytes/row (40 halves: 32 data + 8 pad)
#define HS_TILE (128 * HS_ROW)    // 10240 B
#define HS_STAGE (2 * HS_TILE)    // A + B per stage

template <typename AT, typename OT, int ACT>
__global__ void __launch_bounds__(256, 2) gemm_h_kernel(
    const AT* __restrict__ A, const float* __restrict__ Wt,
    const float* __restrict__ bias, OT* __restrict__ C,
    int Ndim, int Kdim)
{
    __shared__ __align__(16) uint8_t sm[2][HS_STAGE];
    __shared__ float sbias[128];

    const int tid  = threadIdx.x;
    const int lane = tid & 31;
    const int warp = tid >> 5;
    const int wm   = (warp & 1) * 64;
    const int wn   = (warp >> 1) * 32;
    const int m0   = blockIdx.y * 128;
    const int n0   = blockIdx.x * 128;
    const uint32_t sb = smem_u32(sm);

    if (tid < 128) sbias[tid] = bias[n0 + tid];

    const uint32_t a_lm = ((lane & 7) + ((lane >> 3) & 1) * 8) * HS_ROW + ((lane >> 4) & 1) * 16;
    const uint32_t b_lm = (lane & 7) * HS_ROW + ((lane >> 3) & 1) * 16;

    float acc[4][4][4];
#pragma unroll
    for (int i = 0; i < 4; i++)
#pragma unroll
        for (int j = 0; j < 4; j++)
#pragma unroll
            for (int r = 0; r < 4; r++) acc[i][j][r] = 0.0f;

    constexpr bool A_IS_HALF = (sizeof(AT) == 2);
    float4 ra[4];
    uint4  rah[2];
    float4 rb[4];

    auto loadA = [&](int it) {
        if (A_IS_HALF) {
#pragma unroll
            for (int i = 0; i < 2; i++) {
                int c = tid + i * 256;
                int row = c >> 2, kc = (c & 3) * 8;
                rah[i] = *reinterpret_cast<const uint4*>(
                    reinterpret_cast<const __half*>(A) + (size_t)(m0 + row) * Kdim + it * 32 + kc);
            }
        } else {
#pragma unroll
            for (int i = 0; i < 4; i++) {
                int c = tid + i * 256;
                int row = c >> 3, kc = (c & 7) * 4;
                ra[i] = *reinterpret_cast<const float4*>(
                    reinterpret_cast<const float*>(A) + (size_t)(m0 + row) * Kdim + it * 32 + kc);
            }
        }
    };
    auto loadB = [&](int it) {
#pragma unroll
        for (int i = 0; i < 4; i++) {
            int c = tid + i * 256;
            int row = c >> 3, kc = (c & 7) * 4;
            rb[i] = *reinterpret_cast<const float4*>(
                &Wt[(size_t)(n0 + row) * Kdim + it * 32 + kc]);
        }
    };
    auto stsAB = [&](int s) {
        uint8_t* base = &sm[s][0];
        if (A_IS_HALF) {
#pragma unroll
            for (int i = 0; i < 2; i++) {
                int c = tid + i * 256;
                int row = c >> 2, kc = (c & 3) * 8;
                *reinterpret_cast<uint4*>(base + row * HS_ROW + kc * 2) = rah[i];
            }
        } else {
#pragma unroll
            for (int i = 0; i < 4; i++) {
                int c = tid + i * 256;
                int row = c >> 3, kc = (c & 7) * 4;
                *reinterpret_cast<uint2*>(base + row * HS_ROW + kc * 2) =
                    make_uint2(pack_h2(ra[i].x, ra[i].y), pack_h2(ra[i].z, ra[i].w));
            }
        }
        uint8_t* bbase = base + HS_TILE;
#pragma unroll
        for (int i = 0; i < 4; i++) {
            int c = tid + i * 256;
            int row = c >> 3, kc = (c & 7) * 4;
            *reinterpret_cast<uint2*>(bbase + row * HS_ROW + kc * 2) =
                make_uint2(pack_h2(rb[i].x, rb[i].y), pack_h2(rb[i].z, rb[i].w));
        }
    };

    const int T = Kdim >> 5;   // BK = 32
    loadA(0); loadB(0);

    for (int it = 0; it < T; ++it) {
        const int s = it & 1;
        stsAB(s);
        __syncthreads();
        if (it + 1 < T) { loadA(it + 1); loadB(it + 1); }

        const uint32_t sa  = sb + s * HS_STAGE;
        const uint32_t sbm = sa + HS_TILE;
#pragma unroll
        for (int kk = 0; kk < 2; kk++) {
            uint32_t af[4][4], bf[4][2];
#pragma unroll
            for (int im = 0; im < 4; im++)
                ldmx4(af[im], sa + (wm + im * 16) * HS_ROW + a_lm + kk * 32);
#pragma unroll
            for (int in_ = 0; in_ < 4; in_++)
                ldmx2(bf[in_], sbm + (wn + in_ * 8) * HS_ROW + b_lm + kk * 32);
#pragma unroll
            for (int im = 0; im < 4; im++)
#pragma unroll
                for (int in_ = 0; in_ < 4; in_++)
                    mma_f16(acc[im][in_], af[im], bf[in_]);
        }
        __syncthreads();
    }

    // epilogue: bias + activation
    const int g = lane >> 2, t = lane & 3;
#pragma unroll
    for (int im = 0; im < 4; im++) {
        int r0 = m0 + wm + im * 16 + g;
#pragma unroll
        for (int in_ = 0; in_ < 4; in_++) {
            int cl = wn + in_ * 8 + t * 2;
            float b0v = sbias[cl], b1v = sbias[cl + 1];
            float v00 = acc[im][in_][0] + b0v;
            float v01 = acc[im][in_][1] + b1v;
            float v10 = acc[im][in_][2] + b0v;
            float v11 = acc[im][in_][3] + b1v;
            if (ACT == ACT_RELU) {
                v00 = fmaxf(v00, 0.0f); v01 = fmaxf(v01, 0.0f);
                v10 = fmaxf(v10, 0.0f); v11 = fmaxf(v11, 0.0f);
            }
            int c = n0 + cl;
            if (sizeof(OT) == 2) {
                __half* Ch = reinterpret_cast<__half*>(C);
                __half2 lo = __floats2half2_rn(v00, v01);
                __half2 hi = __floats2half2_rn(v10, v11);
                *reinterpret_cast<__half2*>(&Ch[(size_t)r0 * Ndim + c]) = lo;
                *reinterpret_cast<__half2*>(&Ch[(size_t)(r0 + 8) * Ndim + c]) = hi;
            } else {
                float* Cf = reinterpret_cast<float*>(C);
                *reinterpret_cast<float2*>(&Cf[(size_t)r0 * Ndim + c]) = make_float2(v00, v01);
                *reinterpret_cast<float2*>(&Cf[(size_t)(r0 + 8) * Ndim + c]) = make_float2(v10, v11);
            }
        }
    }
}

// ===================== split-K fp16 GEMM for mulv (atomic accumulate) =====================
#define N_STAGES 4
#define SM_GEMM_TOTAL (N_STAGES * HS_STAGE)   // 81920 B dynamic

__global__ void __launch_bounds__(512, 2) gemm_splitk_kernel(
    const __half* __restrict__ A, const __half* __restrict__ Wt,
    float* __restrict__ C, int Ndim, int Kstride, int Kchunk)
{
    extern __shared__ __align__(16) uint8_t dsm[];

    const int tid  = threadIdx.x;
    const int lane = tid & 31;
    const int warp = tid >> 5;
    const int wm   = (warp & 3) * 32;
    const int wn   = (warp >> 2) * 32;
    const int m0   = blockIdx.y * 128;
    const int n0   = blockIdx.x * 128;
    const int koff = blockIdx.z * Kchunk;
    const uint32_t sb = smem_u32(dsm);

    const int rC = tid >> 2;
    const int kC = (tid & 3) * 8;
    const uint32_t dC = (uint32_t)rC * HS_ROW + kC * 2;

    const __half* Ab = A  + (size_t)m0 * Kstride + koff;
    const __half* Bb = Wt + (size_t)n0 * Kstride + koff;

    const int T = Kchunk >> 5;

    auto issue = [&](int it) {
        uint32_t st = sb + (it & (N_STAGES - 1)) * HS_STAGE;
        cp_async16(st + dC,           Ab + (size_t)rC * Kstride + it * 32 + kC);
        cp_async16(st + HS_TILE + dC, Bb + (size_t)rC * Kstride + it * 32 + kC);
        cp_commit();
    };

    const uint32_t a_lm = ((lane & 7) + ((lane >> 3) & 1) * 8) * HS_ROW + ((lane >> 4) & 1) * 16;
    const uint32_t b_lm = ((lane & 7) + ((lane >> 4) & 1) * 8) * HS_ROW + ((lane >> 3) & 1) * 16;

    float acc[2][4][4];
#pragma unroll
    for (int i = 0; i < 2; i++)
#pragma unroll
        for (int j = 0; j < 4; j++)
#pragma unroll
            for (int r = 0; r < 4; r++) acc[i][j][r] = 0.0f;

#pragma unroll
    for (int i = 0; i < N_STAGES - 1; i++) issue(i);

    for (int it = 0; it < T; ++it) {
        cp_wait<N_STAGES - 2>();
        __syncthreads();

        if (it + N_STAGES - 1 < T) issue(it + N_STAGES - 1);
        else cp_commit();

        const uint32_t sa  = sb + (it & (N_STAGES - 1)) * HS_STAGE;
        const uint32_t sbm = sa + HS_TILE;
#pragma unroll
        for (int kk = 0; kk < 2; kk++) {
            uint32_t af[2][4], bf[2][4];
#pragma unroll
            for (int im = 0; im < 2; im++)
                ldmx4(af[im], sa + (wm + im * 16) * HS_ROW + a_lm + kk * 32);
#pragma unroll
            for (int jn = 0; jn < 2; jn++)
                ldmx4(bf[jn], sbm + (wn + jn * 16) * HS_ROW + b_lm + kk * 32);
#pragma unroll
            for (int im = 0; im < 2; im++)
#pragma unroll
                for (int jn = 0; jn < 2; jn++) {
                    mma_f16(acc[im][2 * jn],     af[im], &bf[jn][0]);
                    mma_f16(acc[im][2 * jn + 1], af[im], &bf[jn][2]);
                }
        }
    }

    const int g = lane >> 2, t = lane & 3;
#pragma unroll
    for (int im = 0; im < 2; im++) {
        int r0 = m0 + wm + im * 16 + g;
#pragma unroll
        for (int in_ = 0; in_ < 4; in_++) {
            int c = n0 + wn + in_ * 8 + t * 2;
            atomicAdd(&C[(size_t)r0 * Ndim + c],           acc[im][in_][0]);
            atomicAdd(&C[(size_t)r0 * Ndim + c + 1],       acc[im][in_][1]);
            atomicAdd(&C[(size_t)(r0 + 8) * Ndim + c],     acc[im][in_][2]);
            atomicAdd(&C[(size_t)(r0 + 8) * Ndim + c + 1], acc[im][in_][3]);
        }
    }
}

// ===================== reparameterization + mu/logvar output =====================
__global__ void z_kernel(const float* __restrict__ mulv, const float* __restrict__ eps,
                         const float* __restrict__ mu_b, const float* __restrict__ lv_b,
                         float* __restrict__ z, float* __restrict__ out)
{
    int idx = blockIdx.x * 256 + threadIdx.x;
    if (idx >= B_DIM * Z_DIM) return;
    int b = idx >> 6, j = idx & 63;
    float mu = mulv[(size_t)b * 128 + j]      + mu_b[j];
    float lv = mulv[(size_t)b * 128 + 64 + j] + lv_b[j];
    z[idx] = mu + expf(0.5f * lv) * eps[idx];
    out[OFF_MU + idx] = mu;
    out[OFF_LV + idx] = lv;
}

// ===================== fused decoder: fulcon GEMM + block-diag layers + output =======
#define DEC_SMEM (2 * 64 * 132 * 4)    // 67584 B

__global__ void __launch_bounds__(256) decoder_kernel(
    const float* __restrict__ z,
    const float* __restrict__ m_ful_w, const float* __restrict__ m_ful_b,
    const float* __restrict__ m_h_w,   const float* __restrict__ m_h_b,
    const float* __restrict__ m_out_w, const float* __restrict__ m_out_b,
    const float* __restrict__ c_ful_w, const float* __restrict__ c_ful_b,
    const float* __restrict__ c_h_w,   const float* __restrict__ c_h_b,
    const float* __restrict__ c_out_w, const float* __restrict__ c_out_b,
    float* __restrict__ out)
{
    extern __shared__ float ds[];
    float* Zs = ds;               // [64 k][132]
    float* Ws = ds + 64 * 132;    // [64 k][132]
    __shared__ float sfb[128];

    const bool mean = (blockIdx.z == 0);
    const float* fw = mean ? m_ful_w : c_ful_w;
    const float* fb = mean ? m_ful_b : c_ful_b;
    const float* hw = mean ? m_h_w   : c_h_w;
    const float* hb = mean ? m_h_b   : c_h_b;
    const float* ow = mean ? m_out_w : c_out_w;
    const float* ob = mean ? m_out_b : c_out_b;
    const int out_off = mean ? OFF_XREC : OFF_LCOV;

    const int tid = threadIdx.x;
    const int tx  = tid & 15;
    const int ty  = tid >> 4;
    const int n0  = blockIdx.x * 128;
    const int b0  = blockIdx.y * 128;

#pragma unroll
    for (int it = 0; it < 8; it++) {
        int idx = tid + it * 256;
        int row = idx >> 4, kq = (idx & 15) * 4;
        float4 v = *reinterpret_cast<const float4*>(&z[(size_t)(b0 + row) * 64 + kq]);
        Zs[(kq + 0) * 132 + row] = v.x; Zs[(kq + 1) * 132 + row] = v.y;
        Zs[(kq + 2) * 132 + row] = v.z; Zs[(kq + 3) * 132 + row] = v.w;
    }
#pragma unroll
    for (int it = 0; it < 8; it++) {
        int idx = tid + it * 256;
        int row = idx >> 4, kq = (idx & 15) * 4;
        float4 v = *reinterpret_cast<const float4*>(&fw[(size_t)(n0 + row) * 64 + kq]);
        Ws[(kq + 0) * 132 + row] = v.x; Ws[(kq + 1) * 132 + row] = v.y;
        Ws[(kq + 2) * 132 + row] = v.z; Ws[(kq + 3) * 132 + row] = v.w;
    }
    if (tid < 128) sfb[tid] = fb[n0 + tid];
    __syncthreads();

    float acc[8][8];
#pragma unroll
    for (int i = 0; i < 8; i++)
#pragma unroll
        for (int j = 0; j < 8; j++) acc[i][j] = 0.0f;

#pragma unroll 4
    for (int k = 0; k < 64; k++) {
        float ar[8], br[8];
        *reinterpret_cast<float4*>(&ar[0]) = *reinterpret_cast<const float4*>(&Zs[k * 132 + ty * 8]);
        *reinterpret_cast<float4*>(&ar[4]) = *reinterpret_cast<const float4*>(&Zs[k * 132 + ty * 8 + 4]);
        *reinterpret_cast<float4*>(&br[0]) = *reinterpret_cast<const float4*>(&Ws[k * 132 + tx * 8]);
        *reinterpret_cast<float4*>(&br[4]) = *reinterpret_cast<const float4*>(&Ws[k * 132 + tx * 8 + 4]);
#pragma unroll
        for (int i = 0; i < 8; i++)
#pragma unroll
            for (int j = 0; j < 8; j++)
                acc[i][j] = fmaf(ar[i], br[j], acc[i][j]);
    }
#pragma unroll
    for (int i = 0; i < 8; i++)
#pragma unroll
        for (int j = 0; j < 8; j++)
            acc[i][j] = sigm(acc[i][j] + sfb[tx * 8 + j]);

    __syncthreads();
    float* Os = ds;    // [128 b][64 m]

#pragma unroll
    for (int jj = 0; jj < 4; jj++) {
        int m = (n0 >> 1) + tx * 4 + jj;
        float4 w0 = *reinterpret_cast<const float4*>(&hw[(size_t)m * 4]);
        float4 w1 = *reinterpret_cast<const float4*>(&hw[((size_t)M_DIM + m) * 4]);
        float b00 = hb[2 * m],          b01 = hb[2 * m + 1];
        float b10 = hb[H_DIM + 2 * m],  b11 = hb[H_DIM + 2 * m + 1];
        float2 owv = *reinterpret_cast<const float2*>(&ow[2 * m]);
        float obv = ob[m];
#pragma unroll
        for (int i = 0; i < 8; i++) {
            float a0 = acc[i][2 * jj], a1 = acc[i][2 * jj + 1];
            float t0 = sigm(fmaf(a0, w0.x, fmaf(a1, w0.y, b00)));
            float t1 = sigm(fmaf(a0, w0.z, fmaf(a1, w0.w, b01)));
            a0 = sigm(fmaf(t0, w1.x, fmaf(t1, w1.y, b10)));
            a1 = sigm(fmaf(t0, w1.z, fmaf(t1, w1.w, b11)));
            Os[(ty * 8 + i) * 64 + tx * 4 + jj] = fmaf(a0, owv.x, fmaf(a1, owv.y, obv));
        }
    }
    __syncthreads();

#pragma unroll
    for (int it = 0; it < 8; it++) {
        int idx = tid + it * 256;
        int row = idx >> 4, mq = (idx & 15) * 4;
        float4 v = *reinterpret_cast<const float4*>(&Os[row * 64 + mq]);
        *reinterpret_cast<float4*>(&out[out_off + (size_t)(b0 + row) * M_DIM + (n0 >> 1) + mq]) = v;
    }
}

// ===================== launch =====================
extern "C" void kernel_launch(void* const* d_in, const int* in_sizes, int n_in,
                              void* d_out, int out_size)
{
    const float* x        = (const float*)d_in[0];
    const float* eps      = (const float*)d_in[1];
    const float* enc1_w   = (const float*)d_in[2];
    const float* enc1_b   = (const float*)d_in[3];
    const float* enc2_w   = (const float*)d_in[4];
    const float* enc2_b   = (const float*)d_in[5];
    const float* mu_w     = (const float*)d_in[6];
    const float* mu_b     = (const float*)d_in[7];
    const float* lv_w     = (const float*)d_in[8];
    const float* lv_b     = (const float*)d_in[9];
    const float* m_ful_w  = (const float*)d_in[10];
    const float* m_ful_b  = (const float*)d_in[11];
    const float* m_h_w    = (const float*)d_in[12];
    const float* m_h_b    = (const float*)d_in[13];
    const float* m_out_w  = (const float*)d_in[14];
    const float* m_out_b  = (const float*)d_in[15];
    const float* c_ful_w  = (const float*)d_in[16];
    const float* c_ful_b  = (const float*)d_in[17];
    const float* c_h_w    = (const float*)d_in[18];
    const float* c_h_b    = (const float*)d_in[19];
    const float* c_out_w  = (const float*)d_in[20];
    const float* c_out_b  = (const float*)d_in[21];
    float* out = (float*)d_out;

    __half *wch, *h1h, *h2h;
    float *mulv, *z;
    cudaGetSymbolAddress((void**)&wch,  g_wch);
    cudaGetSymbolAddress((void**)&h1h,  g_h1h);
    cudaGetSymbolAddress((void**)&h2h,  g_h2h);
    cudaGetSymbolAddress((void**)&mulv, g_mulv);
    cudaGetSymbolAddress((void**)&z,    g_z);

    cudaFuncSetAttribute((const void*)gemm_splitk_kernel,
                         cudaFuncAttributeMaxDynamicSharedMemorySize, SM_GEMM_TOTAL);
    cudaFuncSetAttribute((const void*)decoder_kernel,
                         cudaFuncAttributeMaxDynamicSharedMemorySize, DEC_SMEM);

    // ---- tiny prep: mu_w|lv_w -> fp16 (4 MB) ----
    f2hC_kernel<<<(2 * NC8 + 255) / 256, 256>>>(mu_w, lv_w, wch);

    // ---- encoder GEMMs: round-4 kernel, fp32 operands converted in-loop ----
    dim3 g1(M_DIM / 128, B_DIM / 128);   // (32, 8)
    gemm_h_kernel<float,  __half, ACT_RELU><<<g1, 256>>>(x,   enc1_w, enc1_b, h1h, M_DIM, M_DIM);
    gemm_h_kernel<__half, __half, ACT_RELU><<<g1, 256>>>(h1h, enc2_w, enc2_b, h2h, M_DIM, M_DIM);

    // ---- mu / logvar projection: split-K tensor GEMM (atomic accumulate) ----
    cudaMemsetAsync(mulv, 0, B_DIM * 128 * sizeof(float), 0);
    dim3 g2(1, B_DIM / 128, 16);   // N=128 tile, 8 M-tiles, 16 K-chunks of 256
    gemm_splitk_kernel<<<g2, 512, SM_GEMM_TOTAL>>>(h2h, wch, mulv, 128, M_DIM, 256);

    z_kernel<<<(B_DIM * Z_DIM + 255) / 256, 256>>>(mulv, eps, mu_b, lv_b, z, out);

    // ---- fused decoder (both branches) ----
    dim3 g3(H_DIM / 128, B_DIM / 128, 2);
    decoder_kernel<<<g3, 256, DEC_SMEM>>>(
        z,
        m_ful_w, m_ful_b, m_h_w, m_h_b, m_out_w, m_out_b,
        c_ful_w, c_ful_b, c_h_w, c_h_b, c_out_w, c_out_b,
        out);
}

// round 15
// speedup vs baseline: 1.6923x; 1.2848x over previous
#include <cuda_runtime.h>
#include <cuda_fp16.h>
#include <cstdint>
#include <cstddef>

// Problem dims (fixed)
#define B_DIM 1024
#define M_DIM 4096
#define W_DIM 2
#define L_DIM 2
#define Z_DIM 64
#define H_DIM 8192   // M*W

// Output layout: x_recon [B*M], logcov [B*M], mu [B*Z], logvar [B*Z]
#define OFF_XREC  0
#define OFF_LCOV  (B_DIM * M_DIM)
#define OFF_MU    (2 * B_DIM * M_DIM)
#define OFF_LV    (2 * B_DIM * M_DIM + B_DIM * Z_DIM)

// -------- scratch (no allocations allowed; __device__ globals) --------
__device__ __half g_xh  [B_DIM * M_DIM];    // x in fp16
__device__ __half g_w1h [M_DIM * M_DIM];    // enc1_w in fp16
__device__ __half g_w2h [M_DIM * M_DIM];    // enc2_w in fp16
__device__ __half g_wch [128 * M_DIM];      // concat(mu_w, lv_w) in fp16
__device__ __half g_fwh [2 * H_DIM * Z_DIM];// concat(m_ful_w, c_ful_w) in fp16
__device__ __half g_h1h [B_DIM * M_DIM];    // encoder layer-1 out (fp16)
__device__ __half g_h2h [B_DIM * M_DIM];    // encoder layer-2 out (fp16)
__device__ float  g_mulv[B_DIM * 128];
__device__ __half g_zh  [B_DIM * Z_DIM];    // z in fp16
__device__ __half g_ah  [B_DIM * 2 * H_DIM];// fulcon activations, both branches (fp16)

__device__ __forceinline__ float sigm(float x)  { return 1.0f / (1.0f + expf(-x)); }
__device__ __forceinline__ float fsigm(float x) { return __fdividef(1.0f, 1.0f + __expf(-x)); }

#define ACT_NONE 0
#define ACT_RELU 1
#define ACT_SIGMOID 2

// ===================== merged fp32 -> fp16 conversion =====================
#define NX8 (B_DIM * M_DIM / 8)
#define NW8 (M_DIM * M_DIM / 8)
#define NC8 (64 * M_DIM / 8)
#define NF8 (H_DIM * Z_DIM / 8)
#define NTOT8 (NX8 + 2 * NW8 + 2 * NC8 + 2 * NF8)

__device__ __forceinline__ void cvt8(const float* __restrict__ in, __half* __restrict__ out, int j) {
    const float4* p = reinterpret_cast<const float4*>(in) + 2 * (size_t)j;
    float4 a = p[0], b = p[1];
    __half2 h0 = __floats2half2_rn(a.x, a.y);
    __half2 h1 = __floats2half2_rn(a.z, a.w);
    __half2 h2 = __floats2half2_rn(b.x, b.y);
    __half2 h3 = __floats2half2_rn(b.z, b.w);
    uint4 u;
    u.x = *reinterpret_cast<uint32_t*>(&h0);
    u.y = *reinterpret_cast<uint32_t*>(&h1);
    u.z = *reinterpret_cast<uint32_t*>(&h2);
    u.w = *reinterpret_cast<uint32_t*>(&h3);
    reinterpret_cast<uint4*>(out)[j] = u;
}

__global__ void __launch_bounds__(256) f2h7_kernel(
    const float* __restrict__ x,  const float* __restrict__ w1,
    const float* __restrict__ w2, const float* __restrict__ muw,
    const float* __restrict__ lvw,
    const float* __restrict__ mfw, const float* __restrict__ cfw,
    __half* __restrict__ xh, __half* __restrict__ w1h,
    __half* __restrict__ w2h, __half* __restrict__ wch,
    __half* __restrict__ fwh)
{
    int i = blockIdx.x * 256 + threadIdx.x;
    int o = 0;
    if (i < (o += NX8))  { cvt8(x,   xh,  i - (o - NX8)); return; }
    if (i < (o += NW8))  { cvt8(w1,  w1h, i - (o - NW8)); return; }
    if (i < (o += NW8))  { cvt8(w2,  w2h, i - (o - NW8)); return; }
    if (i < (o += NC8))  { cvt8(muw, wch, i - (o - NC8)); return; }
    if (i < (o += NC8))  { cvt8(lvw, wch + 64 * M_DIM, i - (o - NC8)); return; }
    if (i < (o += NF8))  { cvt8(mfw, fwh, i - (o - NF8)); return; }
    if (i < (o += NF8))  { cvt8(cfw, fwh + H_DIM * Z_DIM, i - (o - NF8)); return; }
}

// ===================== common GEMM helpers =====================
__device__ __forceinline__ uint32_t smem_u32(const void* p) {
    uint32_t a;
    asm("{ .reg .u64 t; cvta.to.shared.u64 t, %1; cvt.u32.u64 %0, t; }" : "=r"(a) : "l"(p));
    return a;
}
__device__ __forceinline__ void ldmx4(uint32_t* r, uint32_t addr) {
    asm volatile("ldmatrix.sync.aligned.m8n8.x4.shared.b16 {%0,%1,%2,%3}, [%4];"
                 : "=r"(r[0]), "=r"(r[1]), "=r"(r[2]), "=r"(r[3]) : "r"(addr));
}
__device__ __forceinline__ void mma_f16(float* d, const uint32_t* a, const uint32_t* b) {
    asm volatile(
        "mma.sync.aligned.m16n8k16.row.col.f32.f16.f16.f32 "
        "{%0,%1,%2,%3}, {%4,%5,%6,%7}, {%8,%9}, {%0,%1,%2,%3};\n"
        : "+f"(d[0]), "+f"(d[1]), "+f"(d[2]), "+f"(d[3])
        : "r"(a[0]), "r"(a[1]), "r"(a[2]), "r"(a[3]), "r"(b[0]), "r"(b[1]));
}
__device__ __forceinline__ void cp_async16(uint32_t smem_addr, const void* gptr) {
    asm volatile("cp.async.cg.shared.global [%0], [%1], 16;\n" :: "r"(smem_addr), "l"(gptr));
}
__device__ __forceinline__ void cp_commit() { asm volatile("cp.async.commit_group;\n"); }
template <int N> __device__ __forceinline__ void cp_wait() {
    asm volatile("cp.async.wait_group %0;\n" :: "n"(N));
}

#define HS_ROW   80
#define HS_TILE  (128 * HS_ROW)
#define HS_STAGE (2 * HS_TILE)
#define N_STAGES 4
#define SM_GEMM_TOTAL (N_STAGES * HS_STAGE)   // 81920 B dynamic

// ===================== fp16 cp.async tensor-core GEMM =====================
// Non-split: C = act(A*W^T + bias); bias pointer picked by n0 vs nsplit
// (supports concatenated weight matrices with two bias vectors).
// SPLITK: atomicAdd partials into fp32 C, no bias/act.
template <typename OT, int ACT, bool SPLITK>
__global__ void __launch_bounds__(512, 2) gemm_h16_kernel(
    const __half* __restrict__ A, const __half* __restrict__ Wt,
    const float* __restrict__ bias, const float* __restrict__ bias2, int nsplit,
    OT* __restrict__ C, int Ndim, int Kstride, int Kchunk)
{
    extern __shared__ __align__(16) uint8_t dsm[];
    __shared__ float sbias[128];

    const int tid  = threadIdx.x;
    const int lane = tid & 31;
    const int warp = tid >> 5;
    const int wm   = (warp & 3) * 32;
    const int wn   = (warp >> 2) * 32;
    const int m0   = blockIdx.y * 128;
    const int n0   = blockIdx.x * 128;
    const int koff = SPLITK ? blockIdx.z * Kchunk : 0;
    const uint32_t sb = smem_u32(dsm);

    if (!SPLITK && tid < 128) {
        const float* bp = (n0 < nsplit) ? (bias + n0) : (bias2 + (n0 - nsplit));
        sbias[tid] = bp[tid];
    }

    const int rC = tid >> 2;
    const int kC = (tid & 3) * 8;
    const uint32_t dC = (uint32_t)rC * HS_ROW + kC * 2;

    const __half* Ab = A  + (size_t)m0 * Kstride + koff;
    const __half* Bb = Wt + (size_t)n0 * Kstride + koff;

    const int T = Kchunk >> 5;

    auto issue = [&](int it) {
        uint32_t st = sb + (it & (N_STAGES - 1)) * HS_STAGE;
        cp_async16(st + dC,           Ab + (size_t)rC * Kstride + it * 32 + kC);
        cp_async16(st + HS_TILE + dC, Bb + (size_t)rC * Kstride + it * 32 + kC);
        cp_commit();
    };

    const uint32_t a_lm = ((lane & 7) + ((lane >> 3) & 1) * 8) * HS_ROW + ((lane >> 4) & 1) * 16;
    const uint32_t b_lm = ((lane & 7) + ((lane >> 4) & 1) * 8) * HS_ROW + ((lane >> 3) & 1) * 16;

    float acc[2][4][4];
#pragma unroll
    for (int i = 0; i < 2; i++)
#pragma unroll
        for (int j = 0; j < 4; j++)
#pragma unroll
            for (int r = 0; r < 4; r++) acc[i][j][r] = 0.0f;

    // prologue (guarded: supports short K such as T=2)
#pragma unroll
    for (int i = 0; i < N_STAGES - 1; i++) {
        if (i < T) issue(i);
        else cp_commit();
    }

    for (int it = 0; it < T; ++it) {
        cp_wait<N_STAGES - 2>();
        __syncthreads();

        if (it + N_STAGES - 1 < T) issue(it + N_STAGES - 1);
        else cp_commit();

        const uint32_t sa  = sb + (it & (N_STAGES - 1)) * HS_STAGE;
        const uint32_t sbm = sa + HS_TILE;
#pragma unroll
        for (int kk = 0; kk < 2; kk++) {
            uint32_t af[2][4], bf[2][4];
#pragma unroll
            for (int im = 0; im < 2; im++)
                ldmx4(af[im], sa + (wm + im * 16) * HS_ROW + a_lm + kk * 32);
#pragma unroll
            for (int jn = 0; jn < 2; jn++)
                ldmx4(bf[jn], sbm + (wn + jn * 16) * HS_ROW + b_lm + kk * 32);
#pragma unroll
            for (int im = 0; im < 2; im++)
#pragma unroll
                for (int jn = 0; jn < 2; jn++) {
                    mma_f16(acc[im][2 * jn],     af[im], &bf[jn][0]);
                    mma_f16(acc[im][2 * jn + 1], af[im], &bf[jn][2]);
                }
        }
    }

    const int g = lane >> 2, t = lane & 3;
#pragma unroll
    for (int im = 0; im < 2; im++) {
        int r0 = m0 + wm + im * 16 + g;
#pragma unroll
        for (int in_ = 0; in_ < 4; in_++) {
            int cl = wn + in_ * 8 + t * 2;
            int c = n0 + cl;
            if (SPLITK) {
                float* Cf = reinterpret_cast<float*>(C);
                atomicAdd(&Cf[(size_t)r0 * Ndim + c],           acc[im][in_][0]);
                atomicAdd(&Cf[(size_t)r0 * Ndim + c + 1],       acc[im][in_][1]);
                atomicAdd(&Cf[(size_t)(r0 + 8) * Ndim + c],     acc[im][in_][2]);
                atomicAdd(&Cf[(size_t)(r0 + 8) * Ndim + c + 1], acc[im][in_][3]);
            } else {
                float b0v = sbias[cl], b1v = sbias[cl + 1];
                float v00 = acc[im][in_][0] + b0v;
                float v01 = acc[im][in_][1] + b1v;
                float v10 = acc[im][in_][2] + b0v;
                float v11 = acc[im][in_][3] + b1v;
                if (ACT == ACT_RELU) {
                    v00 = fmaxf(v00, 0.0f); v01 = fmaxf(v01, 0.0f);
                    v10 = fmaxf(v10, 0.0f); v11 = fmaxf(v11, 0.0f);
                }
                if (ACT == ACT_SIGMOID) {
                    v00 = fsigm(v00); v01 = fsigm(v01);
                    v10 = fsigm(v10); v11 = fsigm(v11);
                }
                if (sizeof(OT) == 2) {
                    __half* Ch = reinterpret_cast<__half*>(C);
                    __half2 lo = __floats2half2_rn(v00, v01);
                    __half2 hi = __floats2half2_rn(v10, v11);
                    *reinterpret_cast<__half2*>(&Ch[(size_t)r0 * Ndim + c]) = lo;
                    *reinterpret_cast<__half2*>(&Ch[(size_t)(r0 + 8) * Ndim + c]) = hi;
                } else {
                    float* Cf = reinterpret_cast<float*>(C);
                    *reinterpret_cast<float2*>(&Cf[(size_t)r0 * Ndim + c]) = make_float2(v00, v01);
                    *reinterpret_cast<float2*>(&Cf[(size_t)(r0 + 8) * Ndim + c]) = make_float2(v10, v11);
                }
            }
        }
    }
}

// ===================== reparameterization: mu/logvar out + z (fp16) =====================
__global__ void z_kernel(const float* __restrict__ mulv, const float* __restrict__ eps,
                         const float* __restrict__ mu_b, const float* __restrict__ lv_b,
                         __half* __restrict__ zh, float* __restrict__ out)
{
    int idx = blockIdx.x * 256 + threadIdx.x;
    if (idx >= B_DIM * Z_DIM) return;
    int b = idx >> 6, j = idx & 63;
    float mu = mulv[(size_t)b * 128 + j]      + mu_b[j];
    float lv = mulv[(size_t)b * 128 + 64 + j] + lv_b[j];
    zh[idx] = __float2half(mu + expf(0.5f * lv) * eps[idx]);
    out[OFF_MU + idx] = mu;
    out[OFF_LV + idx] = lv;
}

// ===================== decoder tail: block-diag layers + output (fast sigmoid) ========
__global__ void __launch_bounds__(256) tail_kernel(
    const __half* __restrict__ ah,
    const float* __restrict__ mhw, const float* __restrict__ mhb,
    const float* __restrict__ mow, const float* __restrict__ mob,
    const float* __restrict__ chw, const float* __restrict__ chb,
    const float* __restrict__ cow, const float* __restrict__ cob,
    float* __restrict__ out)
{
    int idx = blockIdx.x * 256 + threadIdx.x;
    if (idx >= B_DIM * M_DIM) return;
    int b = idx >> 12, m = idx & 4095;
    const __half2* arow = reinterpret_cast<const __half2*>(ah + (size_t)b * 2 * H_DIM);

    // ---- mean branch ----
    {
        float2 a = __half22float2(arow[m]);
        float a0 = a.x, a1 = a.y;
#pragma unroll
        for (int l = 0; l < L_DIM; l++) {
            float4 w = *reinterpret_cast<const float4*>(&mhw[((size_t)l * M_DIM + m) * 4]);
            float b0v = mhb[l * H_DIM + 2 * m];
            float b1v = mhb[l * H_DIM + 2 * m + 1];
            float n0 = fsigm(fmaf(a0, w.x, fmaf(a1, w.y, b0v)));
            float n1 = fsigm(fmaf(a0, w.z, fmaf(a1, w.w, b1v)));
            a0 = n0; a1 = n1;
        }
        float2 owv = *reinterpret_cast<const float2*>(&mow[2 * m]);
        out[OFF_XREC + idx] = fmaf(a0, owv.x, fmaf(a1, owv.y, mob[m]));
    }
    // ---- logcov branch ----
    {
        float2 a = __half22float2(arow[M_DIM + m]);
        float a0 = a.x, a1 = a.y;
#pragma unroll
        for (int l = 0; l < L_DIM; l++) {
            float4 w = *reinterpret_cast<const float4*>(&chw[((size_t)l * M_DIM + m) * 4]);
            float b0v = chb[l * H_DIM + 2 * m];
            float b1v = chb[l * H_DIM + 2 * m + 1];
            float n0 = fsigm(fmaf(a0, w.x, fmaf(a1, w.y, b0v)));
            float n1 = fsigm(fmaf(a0, w.z, fmaf(a1, w.w, b1v)));
            a0 = n0; a1 = n1;
        }
        float2 owv = *reinterpret_cast<const float2*>(&cow[2 * m]);
        out[OFF_LCOV + idx] = fmaf(a0, owv.x, fmaf(a1, owv.y, cob[m]));
    }
}

// ===================== launch =====================
extern "C" void kernel_launch(void* const* d_in, const int* in_sizes, int n_in,
                              void* d_out, int out_size)
{
    const float* x        = (const float*)d_in[0];
    const float* eps      = (const float*)d_in[1];
    const float* enc1_w   = (const float*)d_in[2];
    const float* enc1_b   = (const float*)d_in[3];
    const float* enc2_w   = (const float*)d_in[4];
    const float* enc2_b   = (const float*)d_in[5];
    const float* mu_w     = (const float*)d_in[6];
    const float* mu_b     = (const float*)d_in[7];
    const float* lv_w     = (const float*)d_in[8];
    const float* lv_b     = (const float*)d_in[9];
    const float* m_ful_w  = (const float*)d_in[10];
    const float* m_ful_b  = (const float*)d_in[11];
    const float* m_h_w    = (const float*)d_in[12];
    const float* m_h_b    = (const float*)d_in[13];
    const float* m_out_w  = (const float*)d_in[14];
    const float* m_out_b  = (const float*)d_in[15];
    const float* c_ful_w  = (const float*)d_in[16];
    const float* c_ful_b  = (const float*)d_in[17];
    const float* c_h_w    = (const float*)d_in[18];
    const float* c_h_b    = (const float*)d_in[19];
    const float* c_out_w  = (const float*)d_in[20];
    const float* c_out_b  = (const float*)d_in[21];
    float* out = (float*)d_out;

    __half *xh, *w1h, *w2h, *wch, *fwh, *h1h, *h2h, *zh, *ah;
    float *mulv;
    cudaGetSymbolAddress((void**)&xh,   g_xh);
    cudaGetSymbolAddress((void**)&w1h,  g_w1h);
    cudaGetSymbolAddress((void**)&w2h,  g_w2h);
    cudaGetSymbolAddress((void**)&wch,  g_wch);
    cudaGetSymbolAddress((void**)&fwh,  g_fwh);
    cudaGetSymbolAddress((void**)&h1h,  g_h1h);
    cudaGetSymbolAddress((void**)&h2h,  g_h2h);
    cudaGetSymbolAddress((void**)&mulv, g_mulv);
    cudaGetSymbolAddress((void**)&zh,   g_zh);
    cudaGetSymbolAddress((void**)&ah,   g_ah);

    cudaFuncSetAttribute((const void*)gemm_h16_kernel<__half, ACT_RELU, false>,
                         cudaFuncAttributeMaxDynamicSharedMemorySize, SM_GEMM_TOTAL);
    cudaFuncSetAttribute((const void*)gemm_h16_kernel<__half, ACT_SIGMOID, false>,
                         cudaFuncAttributeMaxDynamicSharedMemorySize, SM_GEMM_TOTAL);
    cudaFuncSetAttribute((const void*)gemm_h16_kernel<float, ACT_NONE, true>,
                         cudaFuncAttributeMaxDynamicSharedMemorySize, SM_GEMM_TOTAL);

    // ---- prep: all fp32 -> fp16 conversions in one launch ----
    f2h7_kernel<<<(NTOT8 + 255) / 256, 256>>>(
        x, enc1_w, enc2_w, mu_w, lv_w, m_ful_w, c_ful_w,
        xh, w1h, w2h, wch, fwh);

    // ---- encoder GEMMs (mma.sync fp16 path, at its rate ceiling) ----
    dim3 g1(M_DIM / 128, B_DIM / 128);
    gemm_h16_kernel<__half, ACT_RELU, false><<<g1, 512, SM_GEMM_TOTAL>>>(
        xh,  w1h, enc1_b, nullptr, 1 << 30, h1h, M_DIM, M_DIM, M_DIM);
    gemm_h16_kernel<__half, ACT_RELU, false><<<g1, 512, SM_GEMM_TOTAL>>>(
        h1h, w2h, enc2_b, nullptr, 1 << 30, h2h, M_DIM, M_DIM, M_DIM);

    // ---- mu / logvar projection: split-K tensor GEMM (atomic accumulate) ----
    cudaMemsetAsync(mulv, 0, B_DIM * 128 * sizeof(float), 0);
    dim3 g2(1, B_DIM / 128, 16);   // N=128 tile, 8 M-tiles, 16 K-chunks of 256
    gemm_h16_kernel<float, ACT_NONE, true><<<g2, 512, SM_GEMM_TOTAL>>>(
        h2h, wch, nullptr, nullptr, 0, mulv, 128, M_DIM, 256);

    // ---- z: bias + reparameterize, write fp16 z + mu/logvar outputs ----
    z_kernel<<<(B_DIM * Z_DIM + 255) / 256, 256>>>(mulv, eps, mu_b, lv_b, zh, out);

    // ---- fulcon (both branches concat): tensor GEMM, K=64, sigmoid epilogue ----
    dim3 g4(2 * H_DIM / 128, B_DIM / 128);   // (128, 8) = 1024 CTAs
    gemm_h16_kernel<__half, ACT_SIGMOID, false><<<g4, 512, SM_GEMM_TOTAL>>>(
        zh, fwh, m_ful_b, c_ful_b, H_DIM, ah, 2 * H_DIM, Z_DIM, Z_DIM);

    // ---- decoder tail (both branches, fast sigmoid) ----
    tail_kernel<<<(B_DIM * M_DIM + 255) / 256, 256>>>(
        ah, m_h_w, m_h_b, m_out_w, m_out_b,
        c_h_w, c_h_b, c_out_w, c_out_b, out);
}

// round 16
// speedup vs baseline: 1.9142x; 1.1311x over previous
#include <cuda_runtime.h>
#include <cuda_fp16.h>
#include <cstdint>
#include <cstddef>

// Problem dims (fixed)
#define B_DIM 1024
#define M_DIM 4096
#define W_DIM 2
#define L_DIM 2
#define Z_DIM 64
#define H_DIM 8192   // M*W

// Output layout: x_recon [B*M], logcov [B*M], mu [B*Z], logvar [B*Z]
#define OFF_XREC  0
#define OFF_LCOV  (B_DIM * M_DIM)
#define OFF_MU    (2 * B_DIM * M_DIM)
#define OFF_LV    (2 * B_DIM * M_DIM + B_DIM * Z_DIM)

// -------- scratch (no allocations allowed; __device__ globals) --------
__device__ __half g_xh  [B_DIM * M_DIM];    // x in fp16
__device__ __half g_w1h [M_DIM * M_DIM];    // enc1_w in fp16
__device__ __half g_w2h [M_DIM * M_DIM];    // enc2_w in fp16
__device__ __half g_wch [128 * M_DIM];      // concat(mu_w, lv_w) in fp16
__device__ __half g_fwh [2 * H_DIM * Z_DIM];// concat(m_ful_w, c_ful_w) in fp16
__device__ __half g_h1h [B_DIM * M_DIM];    // encoder layer-1 out (fp16)
__device__ __half g_h2h [B_DIM * M_DIM];    // encoder layer-2 out (fp16)
__device__ float  g_mulv[B_DIM * 128];
__device__ __half g_zh  [B_DIM * Z_DIM];    // z in fp16

__device__ __forceinline__ float fsigm(float x) { return __fdividef(1.0f, 1.0f + __expf(-x)); }

#define ACT_NONE 0
#define ACT_RELU 1

// ===================== conversion sizing =====================
#define NX8 (B_DIM * M_DIM / 8)
#define NW8 (M_DIM * M_DIM / 8)
#define NC8 (64 * M_DIM / 8)
#define NF8 (H_DIM * Z_DIM / 8)
#define NCVT (NW8 + 2 * NC8 + 2 * NF8)   // piggybacked on GEMM1

__device__ __forceinline__ void cvt8(const float* __restrict__ in, __half* __restrict__ out, int j) {
    const float4* p = reinterpret_cast<const float4*>(in) + 2 * (size_t)j;
    float4 a = p[0], b = p[1];
    __half2 h0 = __floats2half2_rn(a.x, a.y);
    __half2 h1 = __floats2half2_rn(a.z, a.w);
    __half2 h2 = __floats2half2_rn(b.x, b.y);
    __half2 h3 = __floats2half2_rn(b.z, b.w);
    uint4 u;
    u.x = *reinterpret_cast<uint32_t*>(&h0);
    u.y = *reinterpret_cast<uint32_t*>(&h1);
    u.z = *reinterpret_cast<uint32_t*>(&h2);
    u.w = *reinterpret_cast<uint32_t*>(&h3);
    reinterpret_cast<uint4*>(out)[j] = u;
}

// prep: x + enc1_w only (GEMM1 prerequisites)
__global__ void __launch_bounds__(256) f2hA_kernel(
    const float* __restrict__ x, const float* __restrict__ w1,
    __half* __restrict__ xh, __half* __restrict__ w1h)
{
    int i = blockIdx.x * 256 + threadIdx.x;
    if (i < NX8)            cvt8(x,  xh,  i);
    else if (i < NX8 + NW8) cvt8(w1, w1h, i - NX8);
}

// ===================== common GEMM helpers =====================
__device__ __forceinline__ uint32_t smem_u32(const void* p) {
    uint32_t a;
    asm("{ .reg .u64 t; cvta.to.shared.u64 t, %1; cvt.u32.u64 %0, t; }" : "=r"(a) : "l"(p));
    return a;
}
__device__ __forceinline__ void ldmx4(uint32_t* r, uint32_t addr) {
    asm volatile("ldmatrix.sync.aligned.m8n8.x4.shared.b16 {%0,%1,%2,%3}, [%4];"
                 : "=r"(r[0]), "=r"(r[1]), "=r"(r[2]), "=r"(r[3]) : "r"(addr));
}
__device__ __forceinline__ void mma_f16(float* d, const uint32_t* a, const uint32_t* b) {
    asm volatile(
        "mma.sync.aligned.m16n8k16.row.col.f32.f16.f16.f32 "
        "{%0,%1,%2,%3}, {%4,%5,%6,%7}, {%8,%9}, {%0,%1,%2,%3};\n"
        : "+f"(d[0]), "+f"(d[1]), "+f"(d[2]), "+f"(d[3])
        : "r"(a[0]), "r"(a[1]), "r"(a[2]), "r"(a[3]), "r"(b[0]), "r"(b[1]));
}
__device__ __forceinline__ void cp_async16(uint32_t smem_addr, const void* gptr) {
    asm volatile("cp.async.cg.shared.global [%0], [%1], 16;\n" :: "r"(smem_addr), "l"(gptr));
}
__device__ __forceinline__ void cp_commit() { asm volatile("cp.async.commit_group;\n"); }
template <int N> __device__ __forceinline__ void cp_wait() {
    asm volatile("cp.async.wait_group %0;\n" :: "n"(N));
}

#define HS_ROW   80
#define HS_TILE  (128 * HS_ROW)
#define HS_STAGE (2 * HS_TILE)
#define N_STAGES 4
#define SM_GEMM_TOTAL (N_STAGES * HS_STAGE)   // 81920 B dynamic

// ===================== encoder GEMM (optionally with conversion piggyback CTAs) =====
// Grid (32 + 5*CVT, 8). CTAs with blockIdx.x >= 32 are grid-stride conversion
// workers (run concurrently with the tensor-bound GEMM; DRAM is nearly idle).
template <int ACT, bool CVT>
__global__ void __launch_bounds__(512, 2) gemm_enc_kernel(
    const __half* __restrict__ A, const __half* __restrict__ Wt,
    const float* __restrict__ bias, __half* __restrict__ C, int Ndim, int Kdim,
    const float* __restrict__ cw2, const float* __restrict__ cmuw,
    const float* __restrict__ clvw, const float* __restrict__ cmfw,
    const float* __restrict__ ccfw,
    __half* __restrict__ dw2, __half* __restrict__ dwc, __half* __restrict__ dfw)
{
    extern __shared__ __align__(16) uint8_t dsm[];
    __shared__ float sbias[128];

    const int tid  = threadIdx.x;

    if (CVT && blockIdx.x >= 32) {
        // conversion worker
        const int wid = (blockIdx.x - 32) * gridDim.y + blockIdx.y;   // 0..39
        const int nth = 40 * 512;
        for (int i = wid * 512 + tid; i < NCVT; i += nth) {
            if (i < NW8)                      cvt8(cw2,  dw2, i);
            else if (i < NW8 + NC8)           cvt8(cmuw, dwc, i - NW8);
            else if (i < NW8 + 2 * NC8)       cvt8(clvw, dwc + 64 * M_DIM, i - NW8 - NC8);
            else if (i < NW8 + 2 * NC8 + NF8) cvt8(cmfw, dfw, i - NW8 - 2 * NC8);
            else                              cvt8(ccfw, dfw + H_DIM * Z_DIM, i - NW8 - 2 * NC8 - NF8);
        }
        return;
    }

    const int lane = tid & 31;
    const int warp = tid >> 5;
    const int wm   = (warp & 3) * 32;
    const int wn   = (warp >> 2) * 32;
    const int m0   = blockIdx.y * 128;
    const int n0   = blockIdx.x * 128;
    const uint32_t sb = smem_u32(dsm);

    if (tid < 128) sbias[tid] = bias[n0 + tid];

    const int rC = tid >> 2;
    const int kC = (tid & 3) * 8;
    const uint32_t dC = (uint32_t)rC * HS_ROW + kC * 2;

    const __half* Ab = A  + (size_t)m0 * Kdim;
    const __half* Bb = Wt + (size_t)n0 * Kdim;

    const int T = Kdim >> 5;

    auto issue = [&](int it) {
        uint32_t st = sb + (it & (N_STAGES - 1)) * HS_STAGE;
        cp_async16(st + dC,           Ab + (size_t)rC * Kdim + it * 32 + kC);
        cp_async16(st + HS_TILE + dC, Bb + (size_t)rC * Kdim + it * 32 + kC);
        cp_commit();
    };

    const uint32_t a_lm = ((lane & 7) + ((lane >> 3) & 1) * 8) * HS_ROW + ((lane >> 4) & 1) * 16;
    const uint32_t b_lm = ((lane & 7) + ((lane >> 4) & 1) * 8) * HS_ROW + ((lane >> 3) & 1) * 16;

    float acc[2][4][4];
#pragma unroll
    for (int i = 0; i < 2; i++)
#pragma unroll
        for (int j = 0; j < 4; j++)
#pragma unroll
            for (int r = 0; r < 4; r++) acc[i][j][r] = 0.0f;

#pragma unroll
    for (int i = 0; i < N_STAGES - 1; i++) issue(i);

    for (int it = 0; it < T; ++it) {
        cp_wait<N_STAGES - 2>();
        __syncthreads();

        if (it + N_STAGES - 1 < T) issue(it + N_STAGES - 1);
        else cp_commit();

        const uint32_t sa  = sb + (it & (N_STAGES - 1)) * HS_STAGE;
        const uint32_t sbm = sa + HS_TILE;
#pragma unroll
        for (int kk = 0; kk < 2; kk++) {
            uint32_t af[2][4], bf[2][4];
#pragma unroll
            for (int im = 0; im < 2; im++)
                ldmx4(af[im], sa + (wm + im * 16) * HS_ROW + a_lm + kk * 32);
#pragma unroll
            for (int jn = 0; jn < 2; jn++)
                ldmx4(bf[jn], sbm + (wn + jn * 16) * HS_ROW + b_lm + kk * 32);
#pragma unroll
            for (int im = 0; im < 2; im++)
#pragma unroll
                for (int jn = 0; jn < 2; jn++) {
                    mma_f16(acc[im][2 * jn],     af[im], &bf[jn][0]);
                    mma_f16(acc[im][2 * jn + 1], af[im], &bf[jn][2]);
                }
        }
    }

    const int g = lane >> 2, t = lane & 3;
#pragma unroll
    for (int im = 0; im < 2; im++) {
        int r0 = m0 + wm + im * 16 + g;
#pragma unroll
        for (int in_ = 0; in_ < 4; in_++) {
            int cl = wn + in_ * 8 + t * 2;
            float b0v = sbias[cl], b1v = sbias[cl + 1];
            float v00 = acc[im][in_][0] + b0v;
            float v01 = acc[im][in_][1] + b1v;
            float v10 = acc[im][in_][2] + b0v;
            float v11 = acc[im][in_][3] + b1v;
            if (ACT == ACT_RELU) {
                v00 = fmaxf(v00, 0.0f); v01 = fmaxf(v01, 0.0f);
                v10 = fmaxf(v10, 0.0f); v11 = fmaxf(v11, 0.0f);
            }
            int c = n0 + cl;
            __half2 lo = __floats2half2_rn(v00, v01);
            __half2 hi = __floats2half2_rn(v10, v11);
            *reinterpret_cast<__half2*>(&C[(size_t)r0 * Ndim + c]) = lo;
            *reinterpret_cast<__half2*>(&C[(size_t)(r0 + 8) * Ndim + c]) = hi;
        }
    }
}

// ===================== split-K fp16 GEMM for mulv (atomic accumulate) =====================
__global__ void __launch_bounds__(512, 2) gemm_splitk_kernel(
    const __half* __restrict__ A, const __half* __restrict__ Wt,
    float* __restrict__ C, int Ndim, int Kstride, int Kchunk)
{
    extern __shared__ __align__(16) uint8_t dsm[];

    const int tid  = threadIdx.x;
    const int lane = tid & 31;
    const int warp = tid >> 5;
    const int wm   = (warp & 3) * 32;
    const int wn   = (warp >> 2) * 32;
    const int m0   = blockIdx.y * 128;
    const int n0   = blockIdx.x * 128;
    const int koff = blockIdx.z * Kchunk;
    const uint32_t sb = smem_u32(dsm);

    const int rC = tid >> 2;
    const int kC = (tid & 3) * 8;
    const uint32_t dC = (uint32_t)rC * HS_ROW + kC * 2;

    const __half* Ab = A  + (size_t)m0 * Kstride + koff;
    const __half* Bb = Wt + (size_t)n0 * Kstride + koff;

    const int T = Kchunk >> 5;

    auto issue = [&](int it) {
        uint32_t st = sb + (it & (N_STAGES - 1)) * HS_STAGE;
        cp_async16(st + dC,           Ab + (size_t)rC * Kstride + it * 32 + kC);
        cp_async16(st + HS_TILE + dC, Bb + (size_t)rC * Kstride + it * 32 + kC);
        cp_commit();
    };

    const uint32_t a_lm = ((lane & 7) + ((lane >> 3) & 1) * 8) * HS_ROW + ((lane >> 4) & 1) * 16;
    const uint32_t b_lm = ((lane & 7) + ((lane >> 4) & 1) * 8) * HS_ROW + ((lane >> 3) & 1) * 16;

    float acc[2][4][4];
#pragma unroll
    for (int i = 0; i < 2; i++)
#pragma unroll
        for (int j = 0; j < 4; j++)
#pragma unroll
            for (int r = 0; r < 4; r++) acc[i][j][r] = 0.0f;

#pragma unroll
    for (int i = 0; i < N_STAGES - 1; i++) issue(i);

    for (int it = 0; it < T; ++it) {
        cp_wait<N_STAGES - 2>();
        __syncthreads();

        if (it + N_STAGES - 1 < T) issue(it + N_STAGES - 1);
        else cp_commit();

        const uint32_t sa  = sb + (it & (N_STAGES - 1)) * HS_STAGE;
        const uint32_t sbm = sa + HS_TILE;
#pragma unroll
        for (int kk = 0; kk < 2; kk++) {
            uint32_t af[2][4], bf[2][4];
#pragma unroll
            for (int im = 0; im < 2; im++)
                ldmx4(af[im], sa + (wm + im * 16) * HS_ROW + a_lm + kk * 32);
#pragma unroll
            for (int jn = 0; jn < 2; jn++)
                ldmx4(bf[jn], sbm + (wn + jn * 16) * HS_ROW + b_lm + kk * 32);
#pragma unroll
            for (int im = 0; im < 2; im++)
#pragma unroll
                for (int jn = 0; jn < 2; jn++) {
                    mma_f16(acc[im][2 * jn],     af[im], &bf[jn][0]);
                    mma_f16(acc[im][2 * jn + 1], af[im], &bf[jn][2]);
                }
        }
    }

    const int g = lane >> 2, t = lane & 3;
#pragma unroll
    for (int im = 0; im < 2; im++) {
        int r0 = m0 + wm + im * 16 + g;
#pragma unroll
        for (int in_ = 0; in_ < 4; in_++) {
            int c = n0 + wn + in_ * 8 + t * 2;
            atomicAdd(&C[(size_t)r0 * Ndim + c],           acc[im][in_][0]);
            atomicAdd(&C[(size_t)r0 * Ndim + c + 1],       acc[im][in_][1]);
            atomicAdd(&C[(size_t)(r0 + 8) * Ndim + c],     acc[im][in_][2]);
            atomicAdd(&C[(size_t)(r0 + 8) * Ndim + c + 1], acc[im][in_][3]);
        }
    }
}

// ===================== reparameterization: mu/logvar out + z (fp16) =====================
__global__ void z_kernel(const float* __restrict__ mulv, const float* __restrict__ eps,
                         const float* __restrict__ mu_b, const float* __restrict__ lv_b,
                         __half* __restrict__ zh, float* __restrict__ out)
{
    int idx = blockIdx.x * 256 + threadIdx.x;
    if (idx >= B_DIM * Z_DIM) return;
    int b = idx >> 6, j = idx & 63;
    float mu = mulv[(size_t)b * 128 + j]      + mu_b[j];
    float lv = mulv[(size_t)b * 128 + 64 + j] + lv_b[j];
    zh[idx] = __float2half(mu + expf(0.5f * lv) * eps[idx]);
    out[OFF_MU + idx] = mu;
    out[OFF_LV + idx] = lv;
}

// ===================== fused decoder GEMM: fulcon + block-diag tail in epilogue ======
// A = zh [B,64], W = fwh [2H,64] (mean rows 0..H-1, cov rows H..2H-1), K=64.
// Epilogue: hidden pair (2m,2m+1) lives in one thread's fragment (c even),
// so the full decoder tail runs in-register; writes out[b][m] directly.
__global__ void __launch_bounds__(512) gemm_dec_kernel(
    const __half* __restrict__ A, const __half* __restrict__ Wt,
    const float* __restrict__ mfb, const float* __restrict__ cfb,
    const float* __restrict__ mhw, const float* __restrict__ mhb,
    const float* __restrict__ mow, const float* __restrict__ mob,
    const float* __restrict__ chw, const float* __restrict__ chb,
    const float* __restrict__ cow, const float* __restrict__ cob,
    float* __restrict__ out)
{
    extern __shared__ __align__(16) uint8_t dsm[];
    __shared__ float sbias[128];

    const int tid  = threadIdx.x;
    const int lane = tid & 31;
    const int warp = tid >> 5;
    const int wm   = (warp & 3) * 32;
    const int wn   = (warp >> 2) * 32;
    const int m0   = blockIdx.y * 128;
    const int n0   = blockIdx.x * 128;
    const uint32_t sb = smem_u32(dsm);

    if (tid < 128) {
        const float* bp = (n0 < H_DIM) ? (mfb + n0) : (cfb + (n0 - H_DIM));
        sbias[tid] = bp[tid];
    }

    const int rC = tid >> 2;
    const int kC = (tid & 3) * 8;
    const uint32_t dC = (uint32_t)rC * HS_ROW + kC * 2;

    const __half* Ab = A  + (size_t)m0 * Z_DIM;
    const __half* Bb = Wt + (size_t)n0 * Z_DIM;

    const int T = 2;   // K = 64

    auto issue = [&](int it) {
        uint32_t st = sb + (it & (N_STAGES - 1)) * HS_STAGE;
        cp_async16(st + dC,           Ab + (size_t)rC * Z_DIM + it * 32 + kC);
        cp_async16(st + HS_TILE + dC, Bb + (size_t)rC * Z_DIM + it * 32 + kC);
        cp_commit();
    };

    const uint32_t a_lm = ((lane & 7) + ((lane >> 3) & 1) * 8) * HS_ROW + ((lane >> 4) & 1) * 16;
    const uint32_t b_lm = ((lane & 7) + ((lane >> 4) & 1) * 8) * HS_ROW + ((lane >> 3) & 1) * 16;

    float acc[2][4][4];
#pragma unroll
    for (int i = 0; i < 2; i++)
#pragma unroll
        for (int j = 0; j < 4; j++)
#pragma unroll
            for (int r = 0; r < 4; r++) acc[i][j][r] = 0.0f;

    // guarded prologue for T=2
#pragma unroll
    for (int i = 0; i < N_STAGES - 1; i++) {
        if (i < T) issue(i);
        else cp_commit();
    }

    for (int it = 0; it < T; ++it) {
        cp_wait<N_STAGES - 2>();
        __syncthreads();
        cp_commit();

        const uint32_t sa  = sb + (it & (N_STAGES - 1)) * HS_STAGE;
        const uint32_t sbm = sa + HS_TILE;
#pragma unroll
        for (int kk = 0; kk < 2; kk++) {
            uint32_t af[2][4], bf[2][4];
#pragma unroll
            for (int im = 0; im < 2; im++)
                ldmx4(af[im], sa + (wm + im * 16) * HS_ROW + a_lm + kk * 32);
#pragma unroll
            for (int jn = 0; jn < 2; jn++)
                ldmx4(bf[jn], sbm + (wn + jn * 16) * HS_ROW + b_lm + kk * 32);
#pragma unroll
            for (int im = 0; im < 2; im++)
#pragma unroll
                for (int jn = 0; jn < 2; jn++) {
                    mma_f16(acc[im][2 * jn],     af[im], &bf[jn][0]);
                    mma_f16(acc[im][2 * jn + 1], af[im], &bf[jn][2]);
                }
        }
    }

    // ---- fused decoder epilogue ----
    const int g = lane >> 2, t = lane & 3;
    const bool cov = (n0 >= H_DIM);
    const float* hw = cov ? chw : mhw;
    const float* hb = cov ? chb : mhb;
    const float* ow = cov ? cow : mow;
    const float* ob = cov ? cob : mob;
    const int out_off = cov ? OFF_LCOV : OFF_XREC;
    const int cbase = cov ? n0 - H_DIM : n0;

#pragma unroll
    for (int in_ = 0; in_ < 4; in_++) {
        int cl = wn + in_ * 8 + t * 2;       // even
        int m  = (cbase + cl) >> 1;
        float fb0 = sbias[cl], fb1 = sbias[cl + 1];
        float4 w0 = *reinterpret_cast<const float4*>(&hw[(size_t)m * 4]);
        float4 w1 = *reinterpret_cast<const float4*>(&hw[((size_t)M_DIM + m) * 4]);
        float b00 = hb[2 * m],          b01 = hb[2 * m + 1];
        float b10 = hb[H_DIM + 2 * m],  b11 = hb[H_DIM + 2 * m + 1];
        float2 owv = *reinterpret_cast<const float2*>(&ow[2 * m]);
        float obv = ob[m];
#pragma unroll
        for (int im = 0; im < 2; im++) {
            int r0 = m0 + wm + im * 16 + g;
#pragma unroll
            for (int rr = 0; rr < 2; rr++) {
                float a0 = fsigm(acc[im][in_][2 * rr]     + fb0);
                float a1 = fsigm(acc[im][in_][2 * rr + 1] + fb1);
                float t0 = fsigm(fmaf(a0, w0.x, fmaf(a1, w0.y, b00)));
                float t1 = fsigm(fmaf(a0, w0.z, fmaf(a1, w0.w, b01)));
                a0 = fsigm(fmaf(t0, w1.x, fmaf(t1, w1.y, b10)));
                a1 = fsigm(fmaf(t0, w1.z, fmaf(t1, w1.w, b11)));
                out[out_off + (size_t)(r0 + rr * 8) * M_DIM + m] =
                    fmaf(a0, owv.x, fmaf(a1, owv.y, obv));
            }
        }
    }
}

// ===================== launch =====================
extern "C" void kernel_launch(void* const* d_in, const int* in_sizes, int n_in,
                              void* d_out, int out_size)
{
    const float* x        = (const float*)d_in[0];
    const float* eps      = (const float*)d_in[1];
    const float* enc1_w   = (const float*)d_in[2];
    const float* enc1_b   = (const float*)d_in[3];
    const float* enc2_w   = (const float*)d_in[4];
    const float* enc2_b   = (const float*)d_in[5];
    const float* mu_w     = (const float*)d_in[6];
    const float* mu_b     = (const float*)d_in[7];
    const float* lv_w     = (const float*)d_in[8];
    const float* lv_b     = (const float*)d_in[9];
    const float* m_ful_w  = (const float*)d_in[10];
    const float* m_ful_b  = (const float*)d_in[11];
    const float* m_h_w    = (const float*)d_in[12];
    const float* m_h_b    = (const float*)d_in[13];
    const float* m_out_w  = (const float*)d_in[14];
    const float* m_out_b  = (const float*)d_in[15];
    const float* c_ful_w  = (const float*)d_in[16];
    const float* c_ful_b  = (const float*)d_in[17];
    const float* c_h_w    = (const float*)d_in[18];
    const float* c_h_b    = (const float*)d_in[19];
    const float* c_out_w  = (const float*)d_in[20];
    const float* c_out_b  = (const float*)d_in[21];
    float* out = (float*)d_out;

    __half *xh, *w1h, *w2h, *wch, *fwh, *h1h, *h2h, *zh;
    float *mulv;
    cudaGetSymbolAddress((void**)&xh,   g_xh);
    cudaGetSymbolAddress((void**)&w1h,  g_w1h);
    cudaGetSymbolAddress((void**)&w2h,  g_w2h);
    cudaGetSymbolAddress((void**)&wch,  g_wch);
    cudaGetSymbolAddress((void**)&fwh,  g_fwh);
    cudaGetSymbolAddress((void**)&h1h,  g_h1h);
    cudaGetSymbolAddress((void**)&h2h,  g_h2h);
    cudaGetSymbolAddress((void**)&mulv, g_mulv);
    cudaGetSymbolAddress((void**)&zh,   g_zh);

    cudaFuncSetAttribute((const void*)gemm_enc_kernel<ACT_RELU, true>,
                         cudaFuncAttributeMaxDynamicSharedMemorySize, SM_GEMM_TOTAL);
    cudaFuncSetAttribute((const void*)gemm_enc_kernel<ACT_RELU, false>,
                         cudaFuncAttributeMaxDynamicSharedMemorySize, SM_GEMM_TOTAL);
    cudaFuncSetAttribute((const void*)gemm_splitk_kernel,
                         cudaFuncAttributeMaxDynamicSharedMemorySize, SM_GEMM_TOTAL);
    cudaFuncSetAttribute((const void*)gemm_dec_kernel,
                         cudaFuncAttributeMaxDynamicSharedMemorySize, SM_GEMM_TOTAL);

    // ---- prep: x + enc1_w only ----
    f2hA_kernel<<<(NX8 + NW8 + 255) / 256, 256>>>(x, enc1_w, xh, w1h);

    // ---- GEMM1 + piggybacked conversions (w2, mu|lv, ful weights) ----
    dim3 g1c(37, B_DIM / 128);   // 256 GEMM CTAs + 40 conversion workers = 296
    gemm_enc_kernel<ACT_RELU, true><<<g1c, 512, SM_GEMM_TOTAL>>>(
        xh, w1h, enc1_b, h1h, M_DIM, M_DIM,
        enc2_w, mu_w, lv_w, m_ful_w, c_ful_w, w2h, wch, fwh);

    // ---- GEMM2 ----
    dim3 g1(32, B_DIM / 128);
    gemm_enc_kernel<ACT_RELU, false><<<g1, 512, SM_GEMM_TOTAL>>>(
        h1h, w2h, enc2_b, h2h, M_DIM, M_DIM,
        nullptr, nullptr, nullptr, nullptr, nullptr, nullptr, nullptr, nullptr);

    // ---- mu / logvar projection: split-K tensor GEMM ----
    cudaMemsetAsync(mulv, 0, B_DIM * 128 * sizeof(float), 0);
    dim3 g2(1, B_DIM / 128, 16);
    gemm_splitk_kernel<<<g2, 512, SM_GEMM_TOTAL>>>(h2h, wch, mulv, 128, M_DIM, 256);

    // ---- z: bias + reparameterize ----
    z_kernel<<<(B_DIM * Z_DIM + 255) / 256, 256>>>(mulv, eps, mu_b, lv_b, zh, out);

    // ---- fused decoder: fulcon GEMM + block-diag tail in epilogue ----
    dim3 g4(2 * H_DIM / 128, B_DIM / 128);   // (128, 8)
    gemm_dec_kernel<<<g4, 512, SM_GEMM_TOTAL>>>(
        zh, fwh, m_ful_b, c_ful_b,
        m_h_w, m_h_b, m_out_w, m_out_b,
        c_h_w, c_h_b, c_out_w, c_out_b, out);
}

// round 17
// speedup vs baseline: 1.9563x; 1.0220x over previous
#include <cuda_runtime.h>
#include <cuda_fp16.h>
#include <cstdint>
#include <cstddef>

// Problem dims (fixed)
#define B_DIM 1024
#define M_DIM 4096
#define W_DIM 2
#define L_DIM 2
#define Z_DIM 64
#define H_DIM 8192   // M*W

// Output layout: x_recon [B*M], logcov [B*M], mu [B*Z], logvar [B*Z]
#define OFF_XREC  0
#define OFF_LCOV  (B_DIM * M_DIM)
#define OFF_MU    (2 * B_DIM * M_DIM)
#define OFF_LV    (2 * B_DIM * M_DIM + B_DIM * Z_DIM)

#define NKSLICE 32   // GEMM2 n-tiles = mulv k-slices

// -------- scratch (no allocations allowed; __device__ globals) --------
__device__ __half g_xh  [B_DIM * M_DIM];    // x in fp16
__device__ __half g_w1h [M_DIM * M_DIM];    // enc1_w in fp16
__device__ __half g_w2h [M_DIM * M_DIM];    // enc2_w in fp16
__device__ __half g_wch [128 * M_DIM];      // concat(mu_w, lv_w) in fp16
__device__ __half g_fwh [2 * H_DIM * Z_DIM];// concat(m_ful_w, c_ful_w) in fp16
__device__ __half g_h1h [B_DIM * M_DIM];    // encoder layer-1 out (fp16)
__device__ float  g_mulvp[NKSLICE * B_DIM * 128];  // mulv partials per k-slice
__device__ __half g_zh  [B_DIM * Z_DIM];    // z in fp16

__device__ __forceinline__ float fsigm(float x) { return __fdividef(1.0f, 1.0f + __expf(-x)); }

#define ACT_RELU 1

// ===================== conversion sizing =====================
#define NX8 (B_DIM * M_DIM / 8)
#define NW8 (M_DIM * M_DIM / 8)
#define NC8 (64 * M_DIM / 8)
#define NF8 (H_DIM * Z_DIM / 8)
#define NCVT (NW8 + 2 * NC8 + 2 * NF8)   // piggybacked on GEMM1

__device__ __forceinline__ void cvt8(const float* __restrict__ in, __half* __restrict__ out, int j) {
    const float4* p = reinterpret_cast<const float4*>(in) + 2 * (size_t)j;
    float4 a = p[0], b = p[1];
    __half2 h0 = __floats2half2_rn(a.x, a.y);
    __half2 h1 = __floats2half2_rn(a.z, a.w);
    __half2 h2 = __floats2half2_rn(b.x, b.y);
    __half2 h3 = __floats2half2_rn(b.z, b.w);
    uint4 u;
    u.x = *reinterpret_cast<uint32_t*>(&h0);
    u.y = *reinterpret_cast<uint32_t*>(&h1);
    u.z = *reinterpret_cast<uint32_t*>(&h2);
    u.w = *reinterpret_cast<uint32_t*>(&h3);
    reinterpret_cast<uint4*>(out)[j] = u;
}

__global__ void __launch_bounds__(256) f2hA_kernel(
    const float* __restrict__ x, const float* __restrict__ w1,
    __half* __restrict__ xh, __half* __restrict__ w1h)
{
    int i = blockIdx.x * 256 + threadIdx.x;
    if (i < NX8)            cvt8(x,  xh,  i);
    else if (i < NX8 + NW8) cvt8(w1, w1h, i - NX8);
}

// ===================== common GEMM helpers =====================
__device__ __forceinline__ uint32_t smem_u32(const void* p) {
    uint32_t a;
    asm("{ .reg .u64 t; cvta.to.shared.u64 t, %1; cvt.u32.u64 %0, t; }" : "=r"(a) : "l"(p));
    return a;
}
__device__ __forceinline__ void ldmx4(uint32_t* r, uint32_t addr) {
    asm volatile("ldmatrix.sync.aligned.m8n8.x4.shared.b16 {%0,%1,%2,%3}, [%4];"
                 : "=r"(r[0]), "=r"(r[1]), "=r"(r[2]), "=r"(r[3]) : "r"(addr));
}
__device__ __forceinline__ void mma_f16(float* d, const uint32_t* a, const uint32_t* b) {
    asm volatile(
        "mma.sync.aligned.m16n8k16.row.col.f32.f16.f16.f32 "
        "{%0,%1,%2,%3}, {%4,%5,%6,%7}, {%8,%9}, {%0,%1,%2,%3};\n"
        : "+f"(d[0]), "+f"(d[1]), "+f"(d[2]), "+f"(d[3])
        : "r"(a[0]), "r"(a[1]), "r"(a[2]), "r"(a[3]), "r"(b[0]), "r"(b[1]));
}
__device__ __forceinline__ void cp_async16(uint32_t smem_addr, const void* gptr) {
    asm volatile("cp.async.cg.shared.global [%0], [%1], 16;\n" :: "r"(smem_addr), "l"(gptr));
}
__device__ __forceinline__ void cp_commit() { asm volatile("cp.async.commit_group;\n"); }
template <int N> __device__ __forceinline__ void cp_wait() {
    asm volatile("cp.async.wait_group %0;\n" :: "n"(N));
}

#define HS_ROW   80
#define HS_TILE  (128 * HS_ROW)
#define HS_STAGE (2 * HS_TILE)
#define N_STAGES 4
#define SM_GEMM_TOTAL (N_STAGES * HS_STAGE)   // 81920 B dynamic

// ===================== GEMM1 (with conversion piggyback CTAs) =====================
template <int ACT, bool CVT>
__global__ void __launch_bounds__(512, 2) gemm_enc_kernel(
    const __half* __restrict__ A, const __half* __restrict__ Wt,
    const float* __restrict__ bias, __half* __restrict__ C, int Ndim, int Kdim,
    const float* __restrict__ cw2, const float* __restrict__ cmuw,
    const float* __restrict__ clvw, const float* __restrict__ cmfw,
    const float* __restrict__ ccfw,
    __half* __restrict__ dw2, __half* __restrict__ dwc, __half* __restrict__ dfw)
{
    extern __shared__ __align__(16) uint8_t dsm[];
    __shared__ float sbias[128];

    const int tid  = threadIdx.x;

    if (CVT && blockIdx.x >= 32) {
        const int wid = (blockIdx.x - 32) * gridDim.y + blockIdx.y;   // 0..39
        const int nth = 40 * 512;
        for (int i = wid * 512 + tid; i < NCVT; i += nth) {
            if (i < NW8)                      cvt8(cw2,  dw2, i);
            else if (i < NW8 + NC8)           cvt8(cmuw, dwc, i - NW8);
            else if (i < NW8 + 2 * NC8)       cvt8(clvw, dwc + 64 * M_DIM, i - NW8 - NC8);
            else if (i < NW8 + 2 * NC8 + NF8) cvt8(cmfw, dfw, i - NW8 - 2 * NC8);
            else                              cvt8(ccfw, dfw + H_DIM * Z_DIM, i - NW8 - 2 * NC8 - NF8);
        }
        return;
    }

    const int lane = tid & 31;
    const int warp = tid >> 5;
    const int wm   = (warp & 3) * 32;
    const int wn   = (warp >> 2) * 32;
    const int m0   = blockIdx.y * 128;
    const int n0   = blockIdx.x * 128;
    const uint32_t sb = smem_u32(dsm);

    if (tid < 128) sbias[tid] = bias[n0 + tid];

    const int rC = tid >> 2;
    const int kC = (tid & 3) * 8;
    const uint32_t dC = (uint32_t)rC * HS_ROW + kC * 2;

    const __half* Ab = A  + (size_t)m0 * Kdim;
    const __half* Bb = Wt + (size_t)n0 * Kdim;

    const int T = Kdim >> 5;

    auto issue = [&](int it) {
        uint32_t st = sb + (it & (N_STAGES - 1)) * HS_STAGE;
        cp_async16(st + dC,           Ab + (size_t)rC * Kdim + it * 32 + kC);
        cp_async16(st + HS_TILE + dC, Bb + (size_t)rC * Kdim + it * 32 + kC);
        cp_commit();
    };

    const uint32_t a_lm = ((lane & 7) + ((lane >> 3) & 1) * 8) * HS_ROW + ((lane >> 4) & 1) * 16;
    const uint32_t b_lm = ((lane & 7) + ((lane >> 4) & 1) * 8) * HS_ROW + ((lane >> 3) & 1) * 16;

    float acc[2][4][4];
#pragma unroll
    for (int i = 0; i < 2; i++)
#pragma unroll
        for (int j = 0; j < 4; j++)
#pragma unroll
            for (int r = 0; r < 4; r++) acc[i][j][r] = 0.0f;

#pragma unroll
    for (int i = 0; i < N_STAGES - 1; i++) issue(i);

    for (int it = 0; it < T; ++it) {
        cp_wait<N_STAGES - 2>();
        __syncthreads();

        if (it + N_STAGES - 1 < T) issue(it + N_STAGES - 1);
        else cp_commit();

        const uint32_t sa  = sb + (it & (N_STAGES - 1)) * HS_STAGE;
        const uint32_t sbm = sa + HS_TILE;
#pragma unroll
        for (int kk = 0; kk < 2; kk++) {
            uint32_t af[2][4], bf[2][4];
#pragma unroll
            for (int im = 0; im < 2; im++)
                ldmx4(af[im], sa + (wm + im * 16) * HS_ROW + a_lm + kk * 32);
#pragma unroll
            for (int jn = 0; jn < 2; jn++)
                ldmx4(bf[jn], sbm + (wn + jn * 16) * HS_ROW + b_lm + kk * 32);
#pragma unroll
            for (int im = 0; im < 2; im++)
#pragma unroll
                for (int jn = 0; jn < 2; jn++) {
                    mma_f16(acc[im][2 * jn],     af[im], &bf[jn][0]);
                    mma_f16(acc[im][2 * jn + 1], af[im], &bf[jn][2]);
                }
        }
    }

    const int g = lane >> 2, t = lane & 3;
#pragma unroll
    for (int im = 0; im < 2; im++) {
        int r0 = m0 + wm + im * 16 + g;
#pragma unroll
        for (int in_ = 0; in_ < 4; in_++) {
            int cl = wn + in_ * 8 + t * 2;
            float b0v = sbias[cl], b1v = sbias[cl + 1];
            float v00 = fmaxf(acc[im][in_][0] + b0v, 0.0f);
            float v01 = fmaxf(acc[im][in_][1] + b1v, 0.0f);
            float v10 = fmaxf(acc[im][in_][2] + b0v, 0.0f);
            float v11 = fmaxf(acc[im][in_][3] + b1v, 0.0f);
            int c = n0 + cl;
            __half2 lo = __floats2half2_rn(v00, v01);
            __half2 hi = __floats2half2_rn(v10, v11);
            *reinterpret_cast<__half2*>(&C[(size_t)r0 * Ndim + c]) = lo;
            *reinterpret_cast<__half2*>(&C[(size_t)(r0 + 8) * Ndim + c]) = hi;
        }
    }
}

// ===================== GEMM2 fused with mulv projection =====================
// Computes h2 tile (ReLU, fp16) in-register, stages it to smem, then multiplies
// by the wch k-slice (128 j x 128 k) and writes a per-k-slice mulv partial
// with plain stores (disjoint b-rows per CTA). h2 never touches global memory.
__global__ void __launch_bounds__(512, 2) gemm_enc2_kernel(
    const __half* __restrict__ A, const __half* __restrict__ Wt,
    const float* __restrict__ bias, const __half* __restrict__ wch,
    float* __restrict__ mulvp, int Kdim)
{
    extern __shared__ __align__(16) uint8_t dsm[];
    __shared__ float sbias[128];

    const int tid  = threadIdx.x;
    const int lane = tid & 31;
    const int warp = tid >> 5;
    const int wm   = (warp & 3) * 32;
    const int wn   = (warp >> 2) * 32;
    const int m0   = blockIdx.y * 128;
    const int n0   = blockIdx.x * 128;
    const uint32_t sb = smem_u32(dsm);

    if (tid < 128) sbias[tid] = bias[n0 + tid];

    const int rC = tid >> 2;
    const int kC = (tid & 3) * 8;
    const uint32_t dC = (uint32_t)rC * HS_ROW + kC * 2;

    const __half* Ab = A  + (size_t)m0 * Kdim;
    const __half* Bb = Wt + (size_t)n0 * Kdim;

    const int T = Kdim >> 5;

    auto issue = [&](int it) {
        uint32_t st = sb + (it & (N_STAGES - 1)) * HS_STAGE;
        cp_async16(st + dC,           Ab + (size_t)rC * Kdim + it * 32 + kC);
        cp_async16(st + HS_TILE + dC, Bb + (size_t)rC * Kdim + it * 32 + kC);
        cp_commit();
    };

    const uint32_t a_lm = ((lane & 7) + ((lane >> 3) & 1) * 8) * HS_ROW + ((lane >> 4) & 1) * 16;
    const uint32_t b_lm = ((lane & 7) + ((lane >> 4) & 1) * 8) * HS_ROW + ((lane >> 3) & 1) * 16;

    float acc[2][4][4];
#pragma unroll
    for (int i = 0; i < 2; i++)
#pragma unroll
        for (int j = 0; j < 4; j++)
#pragma unroll
            for (int r = 0; r < 4; r++) acc[i][j][r] = 0.0f;

#pragma unroll
    for (int i = 0; i < N_STAGES - 1; i++) issue(i);

    for (int it = 0; it < T; ++it) {
        cp_wait<N_STAGES - 2>();
        __syncthreads();

        if (it + N_STAGES - 1 < T) issue(it + N_STAGES - 1);
        else cp_commit();

        const uint32_t sa  = sb + (it & (N_STAGES - 1)) * HS_STAGE;
        const uint32_t sbm = sa + HS_TILE;
#pragma unroll
        for (int kk = 0; kk < 2; kk++) {
            uint32_t af[2][4], bf[2][4];
#pragma unroll
            for (int im = 0; im < 2; im++)
                ldmx4(af[im], sa + (wm + im * 16) * HS_ROW + a_lm + kk * 32);
#pragma unroll
            for (int jn = 0; jn < 2; jn++)
                ldmx4(bf[jn], sbm + (wn + jn * 16) * HS_ROW + b_lm + kk * 32);
#pragma unroll
            for (int im = 0; im < 2; im++)
#pragma unroll
                for (int jn = 0; jn < 2; jn++) {
                    mma_f16(acc[im][2 * jn],     af[im], &bf[jn][0]);
                    mma_f16(acc[im][2 * jn + 1], af[im], &bf[jn][2]);
                }
        }
    }

    // ---- stage post-ReLU h2 tile into smem (chunked-32 layout, stages 0-1) ----
    __syncthreads();   // all mainloop smem reads done before overwrite
    const int g = lane >> 2, t = lane & 3;
#pragma unroll
    for (int im = 0; im < 2; im++) {
        int rl = wm + im * 16 + g;
#pragma unroll
        for (int in_ = 0; in_ < 4; in_++) {
            int cl = wn + in_ * 8 + t * 2;
            float b0v = sbias[cl], b1v = sbias[cl + 1];
            __half2 lo = __floats2half2_rn(fmaxf(acc[im][in_][0] + b0v, 0.0f),
                                           fmaxf(acc[im][in_][1] + b1v, 0.0f));
            __half2 hi = __floats2half2_rn(fmaxf(acc[im][in_][2] + b0v, 0.0f),
                                           fmaxf(acc[im][in_][3] + b1v, 0.0f));
            uint32_t off = (uint32_t)(cl >> 5) * HS_TILE + (cl & 31) * 2;
            *reinterpret_cast<__half2*>(dsm + off + rl * HS_ROW)       = lo;
            *reinterpret_cast<__half2*>(dsm + off + (rl + 8) * HS_ROW) = hi;
        }
    }

    // ---- load wch k-slice [128 j x 128 k] into stages 2-3 ----
#pragma unroll
    for (int i = 0; i < 4; i++) {
        int c = tid + i * 512;              // 0..2047
        int j = c >> 4, seg = c & 15;       // 16 x 8-half segments per row
        uint32_t dst = sb + 4 * HS_TILE + (uint32_t)(seg >> 2) * HS_TILE
                     + j * HS_ROW + (seg & 3) * 16;
        cp_async16(dst, wch + (size_t)j * Kdim + n0 + seg * 8);
    }
    cp_commit();
    cp_wait<0>();
    __syncthreads();

    // ---- mini-GEMM: mulv partial [128 b x 128 j], K = 128 ----
    float acc2[2][4][4];
#pragma unroll
    for (int i = 0; i < 2; i++)
#pragma unroll
        for (int j = 0; j < 4; j++)
#pragma unroll
            for (int r = 0; r < 4; r++) acc2[i][j][r] = 0.0f;

#pragma unroll
    for (int it2 = 0; it2 < 4; it2++) {
        const uint32_t sa  = sb + it2 * HS_TILE;
        const uint32_t sbm = sb + (4 + it2) * HS_TILE;
#pragma unroll
        for (int kk = 0; kk < 2; kk++) {
            uint32_t af[2][4], bf[2][4];
#pragma unroll
            for (int im = 0; im < 2; im++)
                ldmx4(af[im], sa + (wm + im * 16) * HS_ROW + a_lm + kk * 32);
#pragma unroll
            for (int jn = 0; jn < 2; jn++)
                ldmx4(bf[jn], sbm + (wn + jn * 16) * HS_ROW + b_lm + kk * 32);
#pragma unroll
            for (int im = 0; im < 2; im++)
#pragma unroll
                for (int jn = 0; jn < 2; jn++) {
                    mma_f16(acc2[im][2 * jn],     af[im], &bf[jn][0]);
                    mma_f16(acc2[im][2 * jn + 1], af[im], &bf[jn][2]);
                }
        }
    }

    // ---- plain-store partial (this CTA owns rows m0..m0+127 of slice n-tile) ----
    float* P = mulvp + (size_t)blockIdx.x * B_DIM * 128;
#pragma unroll
    for (int im = 0; im < 2; im++) {
        int r0 = m0 + wm + im * 16 + g;
#pragma unroll
        for (int in_ = 0; in_ < 4; in_++) {
            int c = wn + in_ * 8 + t * 2;
            *reinterpret_cast<float2*>(&P[(size_t)r0 * 128 + c]) =
                make_float2(acc2[im][in_][0], acc2[im][in_][1]);
            *reinterpret_cast<float2*>(&P[(size_t)(r0 + 8) * 128 + c]) =
                make_float2(acc2[im][in_][2], acc2[im][in_][3]);
        }
    }
}

// ===================== reparameterization: sum partials + mu/logvar + z ===========
__global__ void z_kernel(const float* __restrict__ mulvp, const float* __restrict__ eps,
                         const float* __restrict__ mu_b, const float* __restrict__ lv_b,
                         __half* __restrict__ zh, float* __restrict__ out)
{
    int idx = blockIdx.x * 256 + threadIdx.x;
    if (idx >= B_DIM * Z_DIM) return;
    int b = idx >> 6, j = idx & 63;
    float mu = mu_b[j], lv = lv_b[j];
#pragma unroll
    for (int s = 0; s < NKSLICE; s++) {
        const float* p = mulvp + ((size_t)s * B_DIM + b) * 128;
        mu += p[j];
        lv += p[64 + j];
    }
    zh[idx] = __float2half(mu + expf(0.5f * lv) * eps[idx]);
    out[OFF_MU + idx] = mu;
    out[OFF_LV + idx] = lv;
}

// ===================== fused decoder GEMM: fulcon + block-diag tail in epilogue ======
__global__ void __launch_bounds__(512) gemm_dec_kernel(
    const __half* __restrict__ A, const __half* __restrict__ Wt,
    const float* __restrict__ mfb, const float* __restrict__ cfb,
    const float* __restrict__ mhw, const float* __restrict__ mhb,
    const float* __restrict__ mow, const float* __restrict__ mob,
    const float* __restrict__ chw, const float* __restrict__ chb,
    const float* __restrict__ cow, const float* __restrict__ cob,
    float* __restrict__ out)
{
    extern __shared__ __align__(16) uint8_t dsm[];
    __shared__ float sbias[128];

    const int tid  = threadIdx.x;
    const int lane = tid & 31;
    const int warp = tid >> 5;
    const int wm   = (warp & 3) * 32;
    const int wn   = (warp >> 2) * 32;
    const int m0   = blockIdx.y * 128;
    const int n0   = blockIdx.x * 128;
    const uint32_t sb = smem_u32(dsm);

    if (tid < 128) {
        const float* bp = (n0 < H_DIM) ? (mfb + n0) : (cfb + (n0 - H_DIM));
        sbias[tid] = bp[tid];
    }

    const int rC = tid >> 2;
    const int kC = (tid & 3) * 8;
    const uint32_t dC = (uint32_t)rC * HS_ROW + kC * 2;

    const __half* Ab = A  + (size_t)m0 * Z_DIM;
    const __half* Bb = Wt + (size_t)n0 * Z_DIM;

    const int T = 2;   // K = 64

    auto issue = [&](int it) {
        uint32_t st = sb + (it & (N_STAGES - 1)) * HS_STAGE;
        cp_async16(st + dC,           Ab + (size_t)rC * Z_DIM + it * 32 + kC);
        cp_async16(st + HS_TILE + dC, Bb + (size_t)rC * Z_DIM + it * 32 + kC);
        cp_commit();
    };

    const uint32_t a_lm = ((lane & 7) + ((lane >> 3) & 1) * 8) * HS_ROW + ((lane >> 4) & 1) * 16;
    const uint32_t b_lm = ((lane & 7) + ((lane >> 4) & 1) * 8) * HS_ROW + ((lane >> 3) & 1) * 16;

    float acc[2][4][4];
#pragma unroll
    for (int i = 0; i < 2; i++)
#pragma unroll
        for (int j = 0; j < 4; j++)
#pragma unroll
            for (int r = 0; r < 4; r++) acc[i][j][r] = 0.0f;

#pragma unroll
    for (int i = 0; i < N_STAGES - 1; i++) {
        if (i < T) issue(i);
        else cp_commit();
    }

    for (int it = 0; it < T; ++it) {
        cp_wait<N_STAGES - 2>();
        __syncthreads();
        cp_commit();

        const uint32_t sa  = sb + (it & (N_STAGES - 1)) * HS_STAGE;
        const uint32_t sbm = sa + HS_TILE;
#pragma unroll
        for (int kk = 0; kk < 2; kk++) {
            uint32_t af[2][4], bf[2][4];
#pragma unroll
            for (int im = 0; im < 2; im++)
                ldmx4(af[im], sa + (wm + im * 16) * HS_ROW + a_lm + kk * 32);
#pragma unroll
            for (int jn = 0; jn < 2; jn++)
                ldmx4(bf[jn], sbm + (wn + jn * 16) * HS_ROW + b_lm + kk * 32);
#pragma unroll
            for (int im = 0; im < 2; im++)
#pragma unroll
                for (int jn = 0; jn < 2; jn++) {
                    mma_f16(acc[im][2 * jn],     af[im], &bf[jn][0]);
                    mma_f16(acc[im][2 * jn + 1], af[im], &bf[jn][2]);
                }
        }
    }

    // ---- fused decoder epilogue ----
    const int g = lane >> 2, t = lane & 3;
    const bool cov = (n0 >= H_DIM);
    const float* hw = cov ? chw : mhw;
    const float* hb = cov ? chb : mhb;
    const float* ow = cov ? cow : mow;
    const float* ob = cov ? cob : mob;
    const int out_off = cov ? OFF_LCOV : OFF_XREC;
    const int cbase = cov ? n0 - H_DIM : n0;

#pragma unroll
    for (int in_ = 0; in_ < 4; in_++) {
        int cl = wn + in_ * 8 + t * 2;       // even
        int m  = (cbase + cl) >> 1;
        float fb0 = sbias[cl], fb1 = sbias[cl + 1];
        float4 w0 = *reinterpret_cast<const float4*>(&hw[(size_t)m * 4]);
        float4 w1 = *reinterpret_cast<const float4*>(&hw[((size_t)M_DIM + m) * 4]);
        float b00 = hb[2 * m],          b01 = hb[2 * m + 1];
        float b10 = hb[H_DIM + 2 * m],  b11 = hb[H_DIM + 2 * m + 1];
        float2 owv = *reinterpret_cast<const float2*>(&ow[2 * m]);
        float obv = ob[m];
#pragma unroll
        for (int im = 0; im < 2; im++) {
            int r0 = m0 + wm + im * 16 + g;
#pragma unroll
            for (int rr = 0; rr < 2; rr++) {
                float a0 = fsigm(acc[im][in_][2 * rr]     + fb0);
                float a1 = fsigm(acc[im][in_][2 * rr + 1] + fb1);
                float t0 = fsigm(fmaf(a0, w0.x, fmaf(a1, w0.y, b00)));
                float t1 = fsigm(fmaf(a0, w0.z, fmaf(a1, w0.w, b01)));
                a0 = fsigm(fmaf(t0, w1.x, fmaf(t1, w1.y, b10)));
                a1 = fsigm(fmaf(t0, w1.z, fmaf(t1, w1.w, b11)));
                out[out_off + (size_t)(r0 + rr * 8) * M_DIM + m] =
                    fmaf(a0, owv.x, fmaf(a1, owv.y, obv));
            }
        }
    }
}

// ===================== launch =====================
extern "C" void kernel_launch(void* const* d_in, const int* in_sizes, int n_in,
                              void* d_out, int out_size)
{
    const float* x        = (const float*)d_in[0];
    const float* eps      = (const float*)d_in[1];
    const float* enc1_w   = (const float*)d_in[2];
    const float* enc1_b   = (const float*)d_in[3];
    const float* enc2_w   = (const float*)d_in[4];
    const float* enc2_b   = (const float*)d_in[5];
    const float* mu_w     = (const float*)d_in[6];
    const float* mu_b     = (const float*)d_in[7];
    const float* lv_w     = (const float*)d_in[8];
    const float* lv_b     = (const float*)d_in[9];
    const float* m_ful_w  = (const float*)d_in[10];
    const float* m_ful_b  = (const float*)d_in[11];
    const float* m_h_w    = (const float*)d_in[12];
    const float* m_h_b    = (const float*)d_in[13];
    const float* m_out_w  = (const float*)d_in[14];
    const float* m_out_b  = (const float*)d_in[15];
    const float* c_ful_w  = (const float*)d_in[16];
    const float* c_ful_b  = (const float*)d_in[17];
    const float* c_h_w    = (const float*)d_in[18];
    const float* c_h_b    = (const float*)d_in[19];
    const float* c_out_w  = (const float*)d_in[20];
    const float* c_out_b  = (const float*)d_in[21];
    float* out = (float*)d_out;

    __half *xh, *w1h, *w2h, *wch, *fwh, *h1h, *zh;
    float *mulvp;
    cudaGetSymbolAddress((void**)&xh,    g_xh);
    cudaGetSymbolAddress((void**)&w1h,   g_w1h);
    cudaGetSymbolAddress((void**)&w2h,   g_w2h);
    cudaGetSymbolAddress((void**)&wch,   g_wch);
    cudaGetSymbolAddress((void**)&fwh,   g_fwh);
    cudaGetSymbolAddress((void**)&h1h,   g_h1h);
    cudaGetSymbolAddress((void**)&mulvp, g_mulvp);
    cudaGetSymbolAddress((void**)&zh,    g_zh);

    cudaFuncSetAttribute((const void*)gemm_enc_kernel<ACT_RELU, true>,
                         cudaFuncAttributeMaxDynamicSharedMemorySize, SM_GEMM_TOTAL);
    cudaFuncSetAttribute((const void*)gemm_enc2_kernel,
                         cudaFuncAttributeMaxDynamicSharedMemorySize, SM_GEMM_TOTAL);
    cudaFuncSetAttribute((const void*)gemm_dec_kernel,
                         cudaFuncAttributeMaxDynamicSharedMemorySize, SM_GEMM_TOTAL);

    // ---- prep: x + enc1_w only ----
    f2hA_kernel<<<(NX8 + NW8 + 255) / 256, 256>>>(x, enc1_w, xh, w1h);

    // ---- GEMM1 + piggybacked conversions (w2, mu|lv, ful weights) ----
    dim3 g1c(37, B_DIM / 128);   // 256 GEMM CTAs + 40 conversion workers = 296
    gemm_enc_kernel<ACT_RELU, true><<<g1c, 512, SM_GEMM_TOTAL>>>(
        xh, w1h, enc1_b, h1h, M_DIM, M_DIM,
        enc2_w, mu_w, lv_w, m_ful_w, c_ful_w, w2h, wch, fwh);

    // ---- GEMM2 fused with mulv projection (h2 never hits DRAM) ----
    dim3 g1(NKSLICE, B_DIM / 128);   // (32, 8)
    gemm_enc2_kernel<<<g1, 512, SM_GEMM_TOTAL>>>(
        h1h, w2h, enc2_b, wch, mulvp, M_DIM);

    // ---- z: sum 32 partials + bias + reparameterize ----
    z_kernel<<<(B_DIM * Z_DIM + 255) / 256, 256>>>(mulvp, eps, mu_b, lv_b, zh, out);

    // ---- fused decoder: fulcon GEMM + block-diag tail in epilogue ----
    dim3 g4(2 * H_DIM / 128, B_DIM / 128);   // (128, 8)
    gemm_dec_kernel<<<g4, 512, SM_GEMM_TOTAL>>>(
        zh, fwh, m_ful_b, c_ful_b,
        m_h_w, m_h_b, m_out_w, m_out_b,
        c_h_w, c_h_b, c_out_w, c_out_b, out);
}